// round 1
// baseline (speedup 1.0000x reference)
#include <cuda_runtime.h>
#include <math.h>

#define D 768
#define NH 12
#define HD 64
#define FF_DIM 3072
#define NTOK 12288
#define NTOK_A 4096   // 8 seqs * 512

// ---------------- scratch (static device allocations are allowed) ----------
__device__ float g_x   [NTOK * D];        // residual copy of concatenated input
__device__ float g_h   [NTOK * D];        // LN output (reused for LN2)
__device__ float g_qkv [NTOK * 3 * D];    // QKV
__device__ float g_att [NTOK * D];        // attention output
__device__ float g_xmid[NTOK * D];        // post-attention residual
__device__ float g_ff  [(size_t)NTOK * FF_DIM]; // MLP hidden

// ---------------- LayerNorm (+ optional gather/copy of residual) -----------
// row = one token (768 elems), 256 threads, 3 elems/thread.
__global__ void ln_kernel(const float* __restrict__ srcA,
                          const float* __restrict__ srcB,
                          int splitRow,
                          const float* __restrict__ gamma,
                          const float* __restrict__ beta,
                          float* __restrict__ out,
                          float* __restrict__ copy)
{
    int row = blockIdx.x;
    const float* src = (row < splitRow) ? srcA + (size_t)row * D
                                        : srcB + (size_t)(row - splitRow) * D;
    int t = threadIdx.x;
    float v0 = src[t], v1 = src[t + 256], v2 = src[t + 512];

    __shared__ float s1[256], s2[256];
    s1[t] = v0 + v1 + v2;
    s2[t] = v0 * v0 + v1 * v1 + v2 * v2;
    __syncthreads();
    for (int s = 128; s > 0; s >>= 1) {
        if (t < s) { s1[t] += s1[t + s]; s2[t] += s2[t + s]; }
        __syncthreads();
    }
    float m    = s1[0] * (1.0f / 768.0f);
    float var  = s2[0] * (1.0f / 768.0f) - m * m;
    float rstd = rsqrtf(var + 1e-5f);

    float* o = out + (size_t)row * D;
    o[t]       = (v0 - m) * rstd * gamma[t]       + beta[t];
    o[t + 256] = (v1 - m) * rstd * gamma[t + 256] + beta[t + 256];
    o[t + 512] = (v2 - m) * rstd * gamma[t + 512] + beta[t + 512];
    if (copy) {
        float* c = copy + (size_t)row * D;
        c[t] = v0; c[t + 256] = v1; c[t + 512] = v2;
    }
}

// ---------------- SGEMM 128x128x8, 256 threads, 8x8 per thread -------------
// C[M,N] = epilogue(A[M,K] @ B[K,N] + bias)
// EPI 0: +bias                EPI 1: res + ls*( +bias )      EPI 2: gelu(+bias)
template <int EPI>
__global__ __launch_bounds__(256)
void sgemm_kernel(const float* __restrict__ A, const float* __restrict__ B,
                  const float* __restrict__ bias, const float* __restrict__ ls,
                  const float* __restrict__ res, float* __restrict__ C,
                  int M, int N, int K)
{
    const int bx = blockIdx.x, by = blockIdx.y;
    __shared__ float As[8 * 128];   // transposed: As[k][m]
    __shared__ float Bs[8 * 128];   // Bs[k][n]

    int tid  = threadIdx.x;
    int rowA = tid >> 1, colA = (tid & 1) * 4;   // 128 rows x 8 cols (float4)
    int rowB = tid >> 5, colB = (tid & 31) * 4;  // 8 rows x 128 cols (float4)
    int tr   = tid >> 4, tc = tid & 15;          // 16x16 thread grid

    const float* Aptr = A + ((size_t)by * 128 + rowA) * K + colA;
    const float* Bptr = B + (size_t)rowB * N + (size_t)bx * 128 + colB;

    float acc[8][8];
    #pragma unroll
    for (int i = 0; i < 8; i++)
        #pragma unroll
        for (int j = 0; j < 8; j++) acc[i][j] = 0.0f;

    for (int kk = 0; kk < K; kk += 8) {
        float4 a4 = *(const float4*)(Aptr + kk);
        float4 b4 = *(const float4*)(Bptr + (size_t)kk * N);
        As[(colA + 0) * 128 + rowA] = a4.x;
        As[(colA + 1) * 128 + rowA] = a4.y;
        As[(colA + 2) * 128 + rowA] = a4.z;
        As[(colA + 3) * 128 + rowA] = a4.w;
        *(float4*)(Bs + rowB * 128 + colB) = b4;
        __syncthreads();

        #pragma unroll
        for (int kd = 0; kd < 8; kd++) {
            float ar[8], br[8];
            #pragma unroll
            for (int i = 0; i < 8; i++) ar[i] = As[kd * 128 + tr * 8 + i];
            #pragma unroll
            for (int j = 0; j < 8; j++) br[j] = Bs[kd * 128 + tc * 8 + j];
            #pragma unroll
            for (int i = 0; i < 8; i++)
                #pragma unroll
                for (int j = 0; j < 8; j++)
                    acc[i][j] += ar[i] * br[j];
        }
        __syncthreads();
    }

    #pragma unroll
    for (int i = 0; i < 8; i++) {
        int row = by * 128 + tr * 8 + i;
        #pragma unroll
        for (int j = 0; j < 8; j++) {
            int col = bx * 128 + tc * 8 + j;
            float v = acc[i][j] + bias[col];
            size_t idx = (size_t)row * N + col;
            if (EPI == 0) {
                C[idx] = v;
            } else if (EPI == 1) {
                C[idx] = res[idx] + ls[col] * v;
            } else {
                C[idx] = 0.5f * v * (1.0f + erff(v * 0.70710678118654752f));
            }
        }
    }
}

// ---------------- Attention -----------------------------------------------
// One block = (seq, head, 16-query tile). 128 threads.
// Two-pass: scores for all n keys in dynamic smem (row stride n+4), then
// row softmax (warp per 4 rows), then P @ V.
__global__ void attn_kernel(const float* __restrict__ qkv,
                            float* __restrict__ out,
                            int n, int token0)
{
    int qtiles = n >> 4;
    int b   = blockIdx.x;
    int qt  = b % qtiles;
    int r   = b / qtiles;
    int head = r % NH;
    int seq  = r / NH;
    size_t base = (size_t)(token0 + seq * n) * (3 * D);
    int ns = n + 4;  // padded row stride (banks)

    extern __shared__ float sm[];
    float* Qs = sm;             // 16 x 64
    float* S  = sm + 16 * 64;   // 16 x ns

    int tid = threadIdx.x;      // 128
    int q0  = qt * 16;
    const float scale = 0.125f; // HD^-0.5

    // load Q tile (scaled)
    for (int i = tid; i < 1024; i += 128) {
        int rq = i >> 6, c = i & 63;
        Qs[i] = qkv[base + (size_t)(q0 + rq) * (3 * D) + head * HD + c] * scale;
    }
    __syncthreads();

    // pass A: S[q][k] = Q . K
    for (int k = tid; k < n; k += 128) {
        const float* Kp = qkv + base + (size_t)k * (3 * D) + D + head * HD;
        float kr[64];
        #pragma unroll
        for (int c4 = 0; c4 < 16; c4++) {
            float4 f = *(const float4*)(Kp + c4 * 4);
            kr[c4 * 4 + 0] = f.x; kr[c4 * 4 + 1] = f.y;
            kr[c4 * 4 + 2] = f.z; kr[c4 * 4 + 3] = f.w;
        }
        #pragma unroll
        for (int q = 0; q < 16; q++) {
            float s = 0.0f;
            #pragma unroll
            for (int c = 0; c < 64; c++) s += Qs[q * 64 + c] * kr[c];
            S[q * ns + k] = s;
        }
    }
    __syncthreads();

    // softmax per row (warp handles 4 rows)
    int warp = tid >> 5, lane = tid & 31;
    for (int q = warp; q < 16; q += 4) {
        float* Sr = S + q * ns;
        float m = -1e30f;
        for (int k = lane; k < n; k += 32) m = fmaxf(m, Sr[k]);
        #pragma unroll
        for (int o = 16; o > 0; o >>= 1) m = fmaxf(m, __shfl_xor_sync(0xffffffffu, m, o));
        float l = 0.0f;
        for (int k = lane; k < n; k += 32) {
            float e = __expf(Sr[k] - m);
            Sr[k] = e; l += e;
        }
        #pragma unroll
        for (int o = 16; o > 0; o >>= 1) l += __shfl_xor_sync(0xffffffffu, l, o);
        float inv = 1.0f / l;
        for (int k = lane; k < n; k += 32) Sr[k] *= inv;
    }
    __syncthreads();

    // pass B: O[q][dg..dg+7] = sum_k P[q][k] * V[k][dg..dg+7]
    int q  = tid >> 3;
    int dg = (tid & 7) * 8;
    float acc[8] = {0, 0, 0, 0, 0, 0, 0, 0};
    const float* Vb = qkv + base + 2 * D + head * HD + dg;
    const float* Sr = S + q * ns;
    for (int k = 0; k < n; k++) {
        float p = Sr[k];
        const float* Vp = Vb + (size_t)k * (3 * D);
        float4 v0 = *(const float4*)(Vp);
        float4 v1 = *(const float4*)(Vp + 4);
        acc[0] += p * v0.x; acc[1] += p * v0.y; acc[2] += p * v0.z; acc[3] += p * v0.w;
        acc[4] += p * v1.x; acc[5] += p * v1.y; acc[6] += p * v1.z; acc[7] += p * v1.w;
    }
    float* O = out + (size_t)(token0 + seq * n + q0 + q) * D + head * HD + dg;
    float4 o0 = make_float4(acc[0], acc[1], acc[2], acc[3]);
    float4 o1 = make_float4(acc[4], acc[5], acc[6], acc[7]);
    *(float4*)(O)     = o0;
    *(float4*)(O + 4) = o1;
}

// ---------------- launch ----------------------------------------------------
extern "C" void kernel_launch(void* const* d_in, const int* in_sizes, int n_in,
                              void* d_out, int out_size)
{
    const float* x1     = (const float*)d_in[0];
    const float* x2     = (const float*)d_in[1];
    const float* ln1_g  = (const float*)d_in[2];
    const float* ln1_b  = (const float*)d_in[3];
    const float* w_qkv  = (const float*)d_in[4];
    const float* b_qkv  = (const float*)d_in[5];
    const float* w_proj = (const float*)d_in[6];
    const float* b_proj = (const float*)d_in[7];
    const float* ls1    = (const float*)d_in[8];
    const float* ln2_g  = (const float*)d_in[9];
    const float* ln2_b  = (const float*)d_in[10];
    const float* w_fc1  = (const float*)d_in[11];
    const float* b_fc1  = (const float*)d_in[12];
    const float* w_fc2  = (const float*)d_in[13];
    const float* b_fc2  = (const float*)d_in[14];
    const float* ls2    = (const float*)d_in[15];
    float* out = (float*)d_out;

    float *xbuf, *hbuf, *qkvbuf, *attbuf, *xmidbuf, *ffbuf;
    cudaGetSymbolAddress((void**)&xbuf,   g_x);
    cudaGetSymbolAddress((void**)&hbuf,   g_h);
    cudaGetSymbolAddress((void**)&qkvbuf, g_qkv);
    cudaGetSymbolAddress((void**)&attbuf, g_att);
    cudaGetSymbolAddress((void**)&xmidbuf,g_xmid);
    cudaGetSymbolAddress((void**)&ffbuf,  g_ff);

    // 1. gather + LN1 (also writes residual copy g_x)
    ln_kernel<<<NTOK, 256>>>(x1, x2, NTOK_A, ln1_g, ln1_b, hbuf, xbuf);

    // 2. QKV GEMM: [12288,768] @ [768,2304] + bias
    sgemm_kernel<0><<<dim3(2304 / 128, NTOK / 128), 256>>>(
        hbuf, w_qkv, b_qkv, nullptr, nullptr, qkvbuf, NTOK, 2304, D);

    // 3. attention (n=512 group, then n=1024 group)
    cudaFuncSetAttribute(attn_kernel, cudaFuncAttributeMaxDynamicSharedMemorySize,
                         (16 * (1024 + 4) + 1024) * 4);
    attn_kernel<<<8 * NH * (512 / 16), 128, (16 * (512 + 4) + 1024) * 4>>>(
        qkvbuf, attbuf, 512, 0);
    attn_kernel<<<8 * NH * (1024 / 16), 128, (16 * (1024 + 4) + 1024) * 4>>>(
        qkvbuf, attbuf, 1024, NTOK_A);

    // 4. proj GEMM + bias, then x = x + ls1 * (.)
    sgemm_kernel<1><<<dim3(768 / 128, NTOK / 128), 256>>>(
        attbuf, w_proj, b_proj, ls1, xbuf, xmidbuf, NTOK, D, D);

    // 5. LN2
    ln_kernel<<<NTOK, 256>>>(xmidbuf, xmidbuf, NTOK, ln2_g, ln2_b, hbuf, nullptr);

    // 6. FC1 GEMM + bias + exact GELU
    sgemm_kernel<2><<<dim3(FF_DIM / 128, NTOK / 128), 256>>>(
        hbuf, w_fc1, b_fc1, nullptr, nullptr, ffbuf, NTOK, FF_DIM, D);

    // 7. FC2 GEMM + bias, then out = xmid + ls2 * (.)
    sgemm_kernel<1><<<dim3(768 / 128, NTOK / 128), 256>>>(
        ffbuf, w_fc2, b_fc2, ls2, xmidbuf, out, NTOK, D, FF_DIM);
}

// round 4
// speedup vs baseline: 1.8659x; 1.8659x over previous
#include <cuda_runtime.h>
#include <cuda_bf16.h>
#include <stdint.h>
#include <math.h>

#define D 768
#define NH 12
#define HD 64
#define FF_DIM 3072
#define NTOK 12288
#define NTOK_A 4096   // 8 seqs * 512

// ---------------- scratch ----------------
__device__ float g_x   [NTOK * D];
__device__ float g_h   [NTOK * D];
__device__ float g_qkv [NTOK * 3 * D];
__device__ float g_att [NTOK * D];
__device__ float g_xmid[NTOK * D];
__device__ float g_ff  [(size_t)NTOK * FF_DIM];

// ---------------- LayerNorm ----------------
__global__ void ln_kernel(const float* __restrict__ srcA,
                          const float* __restrict__ srcB,
                          int splitRow,
                          const float* __restrict__ gamma,
                          const float* __restrict__ beta,
                          float* __restrict__ out,
                          float* __restrict__ copy)
{
    int row = blockIdx.x;
    const float* src = (row < splitRow) ? srcA + (size_t)row * D
                                        : srcB + (size_t)(row - splitRow) * D;
    int t = threadIdx.x;
    float v0 = src[t], v1 = src[t + 256], v2 = src[t + 512];

    __shared__ float s1[256], s2[256];
    s1[t] = v0 + v1 + v2;
    s2[t] = v0 * v0 + v1 * v1 + v2 * v2;
    __syncthreads();
    for (int s = 128; s > 0; s >>= 1) {
        if (t < s) { s1[t] += s1[t + s]; s2[t] += s2[t + s]; }
        __syncthreads();
    }
    float m    = s1[0] * (1.0f / 768.0f);
    float var  = s2[0] * (1.0f / 768.0f) - m * m;
    float rstd = rsqrtf(var + 1e-5f);

    float* o = out + (size_t)row * D;
    o[t]       = (v0 - m) * rstd * gamma[t]       + beta[t];
    o[t + 256] = (v1 - m) * rstd * gamma[t + 256] + beta[t + 256];
    o[t + 512] = (v2 - m) * rstd * gamma[t + 512] + beta[t + 512];
    if (copy) {
        float* c = copy + (size_t)row * D;
        c[t] = v0; c[t + 256] = v1; c[t + 512] = v2;
    }
}

// ---------------- bf16 tensor-core GEMM -------------------------------------
// C[M,N] = epilogue(A_f32[M,K] @ B_f32[K,N] + bias). fp32 global -> bf16 smem.
// 128x128x32 tiles, 256 thr, 8 warps (2x4), warp tile 64x32, mma m16n8k16.
// EPI 0: +bias   EPI 1: res + ls*(+bias)   EPI 2: gelu(+bias)

#define BM 128
#define BN 128
#define BK 32
#define AST 40    // As row stride (bf16): 80B rows -> conflict-free ldmatrix
#define BST 136   // Bs row stride (bf16): 272B rows

__device__ __forceinline__ unsigned pack_bf16(float x, float y) {
    __nv_bfloat162 h = __floats2bfloat162_rn(x, y);
    return *reinterpret_cast<unsigned*>(&h);
}

__device__ __forceinline__ void ldm_x4(unsigned saddr, unsigned* r) {
    asm volatile("ldmatrix.sync.aligned.m8n8.x4.shared.b16 {%0,%1,%2,%3}, [%4];"
                 : "=r"(r[0]), "=r"(r[1]), "=r"(r[2]), "=r"(r[3]) : "r"(saddr));
}
__device__ __forceinline__ void ldm_x4_trans(unsigned saddr, unsigned* r) {
    asm volatile("ldmatrix.sync.aligned.m8n8.x4.trans.shared.b16 {%0,%1,%2,%3}, [%4];"
                 : "=r"(r[0]), "=r"(r[1]), "=r"(r[2]), "=r"(r[3]) : "r"(saddr));
}
__device__ __forceinline__ void mma_bf16(float* c, const unsigned* a, const unsigned* b) {
    asm volatile(
        "mma.sync.aligned.m16n8k16.row.col.f32.bf16.bf16.f32 "
        "{%0,%1,%2,%3}, {%4,%5,%6,%7}, {%8,%9}, {%0,%1,%2,%3};"
        : "+f"(c[0]), "+f"(c[1]), "+f"(c[2]), "+f"(c[3])
        : "r"(a[0]), "r"(a[1]), "r"(a[2]), "r"(a[3]), "r"(b[0]), "r"(b[1]));
}

template <int EPI>
__global__ __launch_bounds__(256)
void gemm_bf16(const float* __restrict__ A, const float* __restrict__ B,
               const float* __restrict__ bias, const float* __restrict__ ls,
               const float* __restrict__ res, float* __restrict__ C,
               int M, int N, int K)
{
    __shared__ __align__(16) __nv_bfloat16 As[2][BM * AST];
    __shared__ __align__(16) __nv_bfloat16 Bs[2][BK * BST];

    const int bx = blockIdx.x, by = blockIdx.y;
    const int tid = threadIdx.x;
    const int warp = tid >> 5, lane = tid & 31;
    const int wm = (warp >> 2) * 64;
    const int wn = (warp & 3) * 32;
    const int group = lane >> 2, tig = lane & 3;

    const int aRow = tid >> 3, aCol = (tid & 7) * 4;    // A: 32 rows x 8 float4
    const int bRow = tid >> 5, bCol = (tid & 31) * 4;   // B: 8 rows x 32 float4

    const float* Ag = A + ((size_t)by * BM + aRow) * K + aCol;
    const float* Bg = B + (size_t)bRow * N + (size_t)bx * BN + bCol;

    float4 aReg[4], bReg[4];
    float acc[4][4][4];
    #pragma unroll
    for (int mt = 0; mt < 4; mt++)
        #pragma unroll
        for (int nt = 0; nt < 4; nt++) {
            acc[mt][nt][0] = 0.f; acc[mt][nt][1] = 0.f;
            acc[mt][nt][2] = 0.f; acc[mt][nt][3] = 0.f;
        }

    const int a_row = wm + (lane & 15);
    const int a_col = (lane >> 4) * 8;
    const int b_krow = ((lane >> 3) & 1) * 8 + (lane & 7);
    const int b_ncol = wn + (lane >> 4) * 8;

    const int iters = K / BK;

    // prologue load tile 0
    #pragma unroll
    for (int i = 0; i < 4; i++)
        aReg[i] = *(const float4*)(Ag + (size_t)(32 * i) * K);
    #pragma unroll
    for (int i = 0; i < 4; i++)
        bReg[i] = *(const float4*)(Bg + (size_t)(8 * i) * N);
    #pragma unroll
    for (int i = 0; i < 4; i++) {
        uint2 p;
        p.x = pack_bf16(aReg[i].x, aReg[i].y);
        p.y = pack_bf16(aReg[i].z, aReg[i].w);
        *(uint2*)(&As[0][(aRow + 32 * i) * AST + aCol]) = p;
    }
    #pragma unroll
    for (int i = 0; i < 4; i++) {
        uint2 p;
        p.x = pack_bf16(bReg[i].x, bReg[i].y);
        p.y = pack_bf16(bReg[i].z, bReg[i].w);
        *(uint2*)(&Bs[0][(bRow + 8 * i) * BST + bCol]) = p;
    }
    __syncthreads();

    for (int it = 0; it < iters; it++) {
        const int s = it & 1;
        const bool more = (it + 1 < iters);
        if (more) {
            const int k0 = (it + 1) * BK;
            #pragma unroll
            for (int i = 0; i < 4; i++)
                aReg[i] = *(const float4*)(Ag + (size_t)(32 * i) * K + k0);
            #pragma unroll
            for (int i = 0; i < 4; i++)
                bReg[i] = *(const float4*)(Bg + (size_t)(k0 + 8 * i) * N);
        }

        unsigned As_base = (unsigned)__cvta_generic_to_shared(&As[s][0]);
        unsigned Bs_base = (unsigned)__cvta_generic_to_shared(&Bs[s][0]);

        #pragma unroll
        for (int kstep = 0; kstep < 2; kstep++) {
            const int k0 = kstep * 16;
            unsigned afr[4][4];
            unsigned bfr[4][2];
            #pragma unroll
            for (int mt = 0; mt < 4; mt++) {
                unsigned ad = As_base +
                    (unsigned)(((a_row + mt * 16) * AST + k0 + a_col) * 2);
                ldm_x4(ad, afr[mt]);
            }
            #pragma unroll
            for (int np = 0; np < 2; np++) {
                unsigned bd = Bs_base +
                    (unsigned)(((k0 + b_krow) * BST + b_ncol + np * 16) * 2);
                unsigned rr[4];
                ldm_x4_trans(bd, rr);
                bfr[2 * np][0] = rr[0]; bfr[2 * np][1] = rr[1];
                bfr[2 * np + 1][0] = rr[2]; bfr[2 * np + 1][1] = rr[3];
            }
            #pragma unroll
            for (int mt = 0; mt < 4; mt++)
                #pragma unroll
                for (int nt = 0; nt < 4; nt++)
                    mma_bf16(acc[mt][nt], afr[mt], bfr[nt]);
        }

        if (more) {
            __syncthreads();
            const int sn = (it + 1) & 1;
            #pragma unroll
            for (int i = 0; i < 4; i++) {
                uint2 p;
                p.x = pack_bf16(aReg[i].x, aReg[i].y);
                p.y = pack_bf16(aReg[i].z, aReg[i].w);
                *(uint2*)(&As[sn][(aRow + 32 * i) * AST + aCol]) = p;
            }
            #pragma unroll
            for (int i = 0; i < 4; i++) {
                uint2 p;
                p.x = pack_bf16(bReg[i].x, bReg[i].y);
                p.y = pack_bf16(bReg[i].z, bReg[i].w);
                *(uint2*)(&Bs[sn][(bRow + 8 * i) * BST + bCol]) = p;
            }
            __syncthreads();
        }
    }

    // epilogue
    #pragma unroll
    for (int mt = 0; mt < 4; mt++) {
        #pragma unroll
        for (int nt = 0; nt < 4; nt++) {
            int row0 = by * BM + wm + mt * 16 + group;
            int col0 = bx * BN + wn + nt * 8 + tig * 2;
            #pragma unroll
            for (int half = 0; half < 2; half++) {
                int row = row0 + half * 8;
                float v0 = acc[mt][nt][2 * half]     + bias[col0];
                float v1 = acc[mt][nt][2 * half + 1] + bias[col0 + 1];
                size_t idx = (size_t)row * N + col0;
                float2 o;
                if (EPI == 0) {
                    o = make_float2(v0, v1);
                } else if (EPI == 1) {
                    float2 r2 = *(const float2*)(res + idx);
                    o = make_float2(r2.x + ls[col0] * v0,
                                    r2.y + ls[col0 + 1] * v1);
                } else {
                    o = make_float2(
                        0.5f * v0 * (1.0f + erff(v0 * 0.70710678118654752f)),
                        0.5f * v1 * (1.0f + erff(v1 * 0.70710678118654752f)));
                }
                *(float2*)(C + idx) = o;
            }
        }
    }
}

// ---------------- Attention ----------------
__global__ void attn_kernel(const float* __restrict__ qkv,
                            float* __restrict__ out,
                            int n, int token0)
{
    int qtiles = n >> 4;
    int b   = blockIdx.x;
    int qt  = b % qtiles;
    int r   = b / qtiles;
    int head = r % NH;
    int seq  = r / NH;
    size_t base = (size_t)(token0 + seq * n) * (3 * D);
    int ns = n + 4;

    extern __shared__ float sm[];
    float* Qs = sm;
    float* S  = sm + 16 * 64;

    int tid = threadIdx.x;
    int q0  = qt * 16;
    const float scale = 0.125f;

    for (int i = tid; i < 1024; i += 128) {
        int rq = i >> 6, c = i & 63;
        Qs[i] = qkv[base + (size_t)(q0 + rq) * (3 * D) + head * HD + c] * scale;
    }
    __syncthreads();

    for (int k = tid; k < n; k += 128) {
        const float* Kp = qkv + base + (size_t)k * (3 * D) + D + head * HD;
        float kr[64];
        #pragma unroll
        for (int c4 = 0; c4 < 16; c4++) {
            float4 f = *(const float4*)(Kp + c4 * 4);
            kr[c4 * 4 + 0] = f.x; kr[c4 * 4 + 1] = f.y;
            kr[c4 * 4 + 2] = f.z; kr[c4 * 4 + 3] = f.w;
        }
        #pragma unroll
        for (int q = 0; q < 16; q++) {
            float s = 0.0f;
            #pragma unroll
            for (int c = 0; c < 64; c++) s += Qs[q * 64 + c] * kr[c];
            S[q * ns + k] = s;
        }
    }
    __syncthreads();

    int warp = tid >> 5, lane = tid & 31;
    for (int q = warp; q < 16; q += 4) {
        float* Sr = S + q * ns;
        float m = -1e30f;
        for (int k = lane; k < n; k += 32) m = fmaxf(m, Sr[k]);
        #pragma unroll
        for (int o = 16; o > 0; o >>= 1) m = fmaxf(m, __shfl_xor_sync(0xffffffffu, m, o));
        float l = 0.0f;
        for (int k = lane; k < n; k += 32) {
            float e = __expf(Sr[k] - m);
            Sr[k] = e; l += e;
        }
        #pragma unroll
        for (int o = 16; o > 0; o >>= 1) l += __shfl_xor_sync(0xffffffffu, l, o);
        float inv = 1.0f / l;
        for (int k = lane; k < n; k += 32) Sr[k] *= inv;
    }
    __syncthreads();

    int q  = tid >> 3;
    int dg = (tid & 7) * 8;
    float acc[8] = {0, 0, 0, 0, 0, 0, 0, 0};
    const float* Vb = qkv + base + 2 * D + head * HD + dg;
    const float* Sr = S + q * ns;
    for (int k = 0; k < n; k++) {
        float p = Sr[k];
        const float* Vp = Vb + (size_t)k * (3 * D);
        float4 v0 = *(const float4*)(Vp);
        float4 v1 = *(const float4*)(Vp + 4);
        acc[0] += p * v0.x; acc[1] += p * v0.y; acc[2] += p * v0.z; acc[3] += p * v0.w;
        acc[4] += p * v1.x; acc[5] += p * v1.y; acc[6] += p * v1.z; acc[7] += p * v1.w;
    }
    float* O = out + (size_t)(token0 + seq * n + q0 + q) * D + head * HD + dg;
    *(float4*)(O)     = make_float4(acc[0], acc[1], acc[2], acc[3]);
    *(float4*)(O + 4) = make_float4(acc[4], acc[5], acc[6], acc[7]);
}

// ---------------- launch ----------------
extern "C" void kernel_launch(void* const* d_in, const int* in_sizes, int n_in,
                              void* d_out, int out_size)
{
    const float* x1     = (const float*)d_in[0];
    const float* x2     = (const float*)d_in[1];
    const float* ln1_g  = (const float*)d_in[2];
    const float* ln1_b  = (const float*)d_in[3];
    const float* w_qkv  = (const float*)d_in[4];
    const float* b_qkv  = (const float*)d_in[5];
    const float* w_proj = (const float*)d_in[6];
    const float* b_proj = (const float*)d_in[7];
    const float* ls1    = (const float*)d_in[8];
    const float* ln2_g  = (const float*)d_in[9];
    const float* ln2_b  = (const float*)d_in[10];
    const float* w_fc1  = (const float*)d_in[11];
    const float* b_fc1  = (const float*)d_in[12];
    const float* w_fc2  = (const float*)d_in[13];
    const float* b_fc2  = (const float*)d_in[14];
    const float* ls2    = (const float*)d_in[15];
    float* out = (float*)d_out;

    float *xbuf, *hbuf, *qkvbuf, *attbuf, *xmidbuf, *ffbuf;
    cudaGetSymbolAddress((void**)&xbuf,   g_x);
    cudaGetSymbolAddress((void**)&hbuf,   g_h);
    cudaGetSymbolAddress((void**)&qkvbuf, g_qkv);
    cudaGetSymbolAddress((void**)&attbuf, g_att);
    cudaGetSymbolAddress((void**)&xmidbuf,g_xmid);
    cudaGetSymbolAddress((void**)&ffbuf,  g_ff);

    // 1. gather + LN1
    ln_kernel<<<NTOK, 256>>>(x1, x2, NTOK_A, ln1_g, ln1_b, hbuf, xbuf);

    // 2. QKV GEMM
    gemm_bf16<0><<<dim3(2304 / BN, NTOK / BM), 256>>>(
        hbuf, w_qkv, b_qkv, nullptr, nullptr, qkvbuf, NTOK, 2304, D);

    // 3. attention
    cudaFuncSetAttribute(attn_kernel, cudaFuncAttributeMaxDynamicSharedMemorySize,
                         (16 * (1024 + 4) + 1024) * 4);
    attn_kernel<<<8 * NH * (512 / 16), 128, (16 * (512 + 4) + 1024) * 4>>>(
        qkvbuf, attbuf, 512, 0);
    attn_kernel<<<8 * NH * (1024 / 16), 128, (16 * (1024 + 4) + 1024) * 4>>>(
        qkvbuf, attbuf, 1024, NTOK_A);

    // 4. proj GEMM + layerscale + residual
    gemm_bf16<1><<<dim3(768 / BN, NTOK / BM), 256>>>(
        attbuf, w_proj, b_proj, ls1, xbuf, xmidbuf, NTOK, D, D);

    // 5. LN2
    ln_kernel<<<NTOK, 256>>>(xmidbuf, xmidbuf, NTOK, ln2_g, ln2_b, hbuf, nullptr);

    // 6. FC1 GEMM + GELU
    gemm_bf16<2><<<dim3(FF_DIM / BN, NTOK / BM), 256>>>(
        hbuf, w_fc1, b_fc1, nullptr, nullptr, ffbuf, NTOK, FF_DIM, D);

    // 7. FC2 GEMM + layerscale + residual
    gemm_bf16<1><<<dim3(768 / BN, NTOK / BM), 256>>>(
        ffbuf, w_fc2, b_fc2, ls2, xmidbuf, out, NTOK, D, FF_DIM);
}

// round 6
// speedup vs baseline: 2.3754x; 1.2731x over previous
#include <cuda_runtime.h>
#include <cuda_bf16.h>
#include <stdint.h>
#include <math.h>

#define D 768
#define NH 12
#define HD 64
#define FF_DIM 3072
#define NTOK 12288
#define NTOK_A 4096   // 8 seqs * 512

typedef __nv_bfloat16 bf16;
typedef __nv_bfloat162 bf162;

// ---------------- scratch ----------------
__device__ float g_x   [NTOK * D];                 // residual (fp32)
__device__ float g_xmid[NTOK * D];                 // post-attn residual (fp32)
__device__ bf16  g_h   [NTOK * D];                 // LN out (bf16)
__device__ bf16  g_qkvh[(size_t)NTOK * 3 * D];     // QKV (bf16)
__device__ bf16  g_atth[NTOK * D];                 // attention out (bf16)
__device__ bf16  g_ffh [(size_t)NTOK * FF_DIM];    // GELU out (bf16)
// bf16 weights
__device__ bf16  g_wqkv [D * 3 * D];
__device__ bf16  g_wproj[D * D];
__device__ bf16  g_wfc1 [D * FF_DIM];
__device__ bf16  g_wfc2 [FF_DIM * D];

// ---------------- fp32 -> bf16 convert ----------------
__global__ void cvt_kernel(const float* __restrict__ src, bf16* __restrict__ dst, int n)
{
    int i = (blockIdx.x * 256 + threadIdx.x) * 4;
    int stride = gridDim.x * 256 * 4;
    for (; i < n; i += stride) {
        float4 f = *(const float4*)(src + i);
        bf162 p0 = __floats2bfloat162_rn(f.x, f.y);
        bf162 p1 = __floats2bfloat162_rn(f.z, f.w);
        *(bf162*)(dst + i)     = p0;
        *(bf162*)(dst + i + 2) = p1;
    }
}

// ---------------- LayerNorm (fp32 in, bf16 out, optional fp32 copy) --------
__global__ void ln_kernel(const float* __restrict__ srcA,
                          const float* __restrict__ srcB,
                          int splitRow,
                          const float* __restrict__ gamma,
                          const float* __restrict__ beta,
                          bf16* __restrict__ out,
                          float* __restrict__ copy)
{
    int row = blockIdx.x;
    const float* src = (row < splitRow) ? srcA + (size_t)row * D
                                        : srcB + (size_t)(row - splitRow) * D;
    int t = threadIdx.x;
    float v0 = src[t], v1 = src[t + 256], v2 = src[t + 512];

    __shared__ float s1[256], s2[256];
    s1[t] = v0 + v1 + v2;
    s2[t] = v0 * v0 + v1 * v1 + v2 * v2;
    __syncthreads();
    for (int s = 128; s > 0; s >>= 1) {
        if (t < s) { s1[t] += s1[t + s]; s2[t] += s2[t + s]; }
        __syncthreads();
    }
    float m    = s1[0] * (1.0f / 768.0f);
    float var  = s2[0] * (1.0f / 768.0f) - m * m;
    float rstd = rsqrtf(var + 1e-5f);

    bf16* o = out + (size_t)row * D;
    o[t]       = __float2bfloat16((v0 - m) * rstd * gamma[t]       + beta[t]);
    o[t + 256] = __float2bfloat16((v1 - m) * rstd * gamma[t + 256] + beta[t + 256]);
    o[t + 512] = __float2bfloat16((v2 - m) * rstd * gamma[t + 512] + beta[t + 512]);
    if (copy) {
        float* c = copy + (size_t)row * D;
        c[t] = v0; c[t + 256] = v1; c[t + 512] = v2;
    }
}

// ---------------- bf16 tensor-core GEMM with cp.async (3 stages) -----------
// C[M,N] = epilogue(A_bf16[M,K] @ B_bf16[K,N] + bias)
// EPI 0: +bias -> bf16      EPI 1: res + ls*(+bias) -> fp32
// EPI 2: gelu(+bias) -> bf16

#define BM 128
#define BN 128
#define BK 32
#define AST 40     // As row stride (bf16): 80B
#define BST 136    // Bs row stride (bf16): 272B
#define STAGES 3
#define A_STAGE (BM * AST)             // 5120 bf16
#define B_STAGE (BK * BST)             // 4352 bf16
#define GEMM_SMEM ((STAGES * (A_STAGE + B_STAGE)) * 2)   // 56832 B

__device__ __forceinline__ void cp_async16(unsigned saddr, const void* gptr) {
    asm volatile("cp.async.cg.shared.global [%0], [%1], 16;" :: "r"(saddr), "l"(gptr));
}
__device__ __forceinline__ void cp_commit() {
    asm volatile("cp.async.commit_group;");
}
template <int N>
__device__ __forceinline__ void cp_wait() {
    asm volatile("cp.async.wait_group %0;" :: "n"(N));
}
__device__ __forceinline__ void ldm_x4(unsigned saddr, unsigned* r) {
    asm volatile("ldmatrix.sync.aligned.m8n8.x4.shared.b16 {%0,%1,%2,%3}, [%4];"
                 : "=r"(r[0]), "=r"(r[1]), "=r"(r[2]), "=r"(r[3]) : "r"(saddr));
}
__device__ __forceinline__ void ldm_x4_trans(unsigned saddr, unsigned* r) {
    asm volatile("ldmatrix.sync.aligned.m8n8.x4.trans.shared.b16 {%0,%1,%2,%3}, [%4];"
                 : "=r"(r[0]), "=r"(r[1]), "=r"(r[2]), "=r"(r[3]) : "r"(saddr));
}
__device__ __forceinline__ void mma_bf16(float* c, const unsigned* a, const unsigned* b) {
    asm volatile(
        "mma.sync.aligned.m16n8k16.row.col.f32.bf16.bf16.f32 "
        "{%0,%1,%2,%3}, {%4,%5,%6,%7}, {%8,%9}, {%0,%1,%2,%3};"
        : "+f"(c[0]), "+f"(c[1]), "+f"(c[2]), "+f"(c[3])
        : "r"(a[0]), "r"(a[1]), "r"(a[2]), "r"(a[3]), "r"(b[0]), "r"(b[1]));
}

// stage issue helper (no lambda: explicit args)
__device__ __forceinline__ void gemm_issue_stage(
    const bf16* AgBase, const bf16* BgBase, bf16* As, bf16* Bs,
    int kt, int s, int K, int N,
    int aRow0, int aRow1, int aChunk0, int bRow0, int bRow1, int bChunk0)
{
    const bf16* Ag = AgBase + kt * BK;
    bf16* Asb = As + s * A_STAGE;
    cp_async16((unsigned)__cvta_generic_to_shared(Asb + aRow0 * AST + aChunk0),
               Ag + (size_t)aRow0 * K + aChunk0);
    cp_async16((unsigned)__cvta_generic_to_shared(Asb + aRow1 * AST + aChunk0),
               Ag + (size_t)aRow1 * K + aChunk0);
    const bf16* Bg = BgBase + (size_t)(kt * BK) * N;
    bf16* Bsb = Bs + s * B_STAGE;
    cp_async16((unsigned)__cvta_generic_to_shared(Bsb + bRow0 * BST + bChunk0),
               Bg + (size_t)bRow0 * N + bChunk0);
    cp_async16((unsigned)__cvta_generic_to_shared(Bsb + bRow1 * BST + bChunk0),
               Bg + (size_t)bRow1 * N + bChunk0);
    cp_commit();
}

template <int EPI>
__global__ __launch_bounds__(256)
void gemm_bf16(const bf16* __restrict__ A, const bf16* __restrict__ B,
               const float* __restrict__ bias, const float* __restrict__ ls,
               const float* __restrict__ res, void* __restrict__ Cout,
               int M, int N, int K)
{
    extern __shared__ __align__(16) char smem_raw[];
    bf16* As = (bf16*)smem_raw;                     // [STAGES][A_STAGE]
    bf16* Bs = As + STAGES * A_STAGE;               // [STAGES][B_STAGE]

    const int bx = blockIdx.x, by = blockIdx.y;
    const int tid = threadIdx.x;
    const int warp = tid >> 5, lane = tid & 31;
    const int wm = (warp >> 2) * 64;
    const int wn = (warp & 3) * 32;
    const int group = lane >> 2, tig = lane & 3;

    // cp.async staging layout
    const int aRow0 = tid >> 2,  aChunk0 = (tid & 3) * 8;
    const int aRow1 = aRow0 + 64;
    const int bRow0 = tid >> 4,  bChunk0 = (tid & 15) * 8;
    const int bRow1 = bRow0 + 16;

    const bf16* AgBase = A + (size_t)(by * BM) * K;
    const bf16* BgBase = B + (size_t)(bx * BN);

    const int iters = K / BK;

    float acc[4][4][4];
    #pragma unroll
    for (int mt = 0; mt < 4; mt++)
        #pragma unroll
        for (int nt = 0; nt < 4; nt++) {
            acc[mt][nt][0] = 0.f; acc[mt][nt][1] = 0.f;
            acc[mt][nt][2] = 0.f; acc[mt][nt][3] = 0.f;
        }

    const int a_row = wm + (lane & 15);
    const int a_col = (lane >> 4) * 8;
    const int b_krow = ((lane >> 3) & 1) * 8 + (lane & 7);
    const int b_ncol = wn + (lane >> 4) * 8;

    gemm_issue_stage(AgBase, BgBase, As, Bs, 0, 0, K, N,
                     aRow0, aRow1, aChunk0, bRow0, bRow1, bChunk0);
    gemm_issue_stage(AgBase, BgBase, As, Bs, 1, 1, K, N,
                     aRow0, aRow1, aChunk0, bRow0, bRow1, bChunk0);

    for (int it = 0; it < iters; it++) {
        cp_wait<STAGES - 2>();
        __syncthreads();

        const int s = it % STAGES;
        unsigned As_base = (unsigned)__cvta_generic_to_shared(As + s * A_STAGE);
        unsigned Bs_base = (unsigned)__cvta_generic_to_shared(Bs + s * B_STAGE);

        #pragma unroll
        for (int kstep = 0; kstep < 2; kstep++) {
            const int k0 = kstep * 16;
            unsigned afr[4][4];
            unsigned bfr[4][2];
            #pragma unroll
            for (int mt = 0; mt < 4; mt++) {
                unsigned ad = As_base +
                    (unsigned)(((a_row + mt * 16) * AST + k0 + a_col) * 2);
                ldm_x4(ad, afr[mt]);
            }
            #pragma unroll
            for (int np = 0; np < 2; np++) {
                unsigned bd = Bs_base +
                    (unsigned)(((k0 + b_krow) * BST + b_ncol + np * 16) * 2);
                unsigned rr[4];
                ldm_x4_trans(bd, rr);
                bfr[2 * np][0] = rr[0]; bfr[2 * np][1] = rr[1];
                bfr[2 * np + 1][0] = rr[2]; bfr[2 * np + 1][1] = rr[3];
            }
            #pragma unroll
            for (int mt = 0; mt < 4; mt++)
                #pragma unroll
                for (int nt = 0; nt < 4; nt++)
                    mma_bf16(acc[mt][nt], afr[mt], bfr[nt]);
        }

        __syncthreads();
        if (it + STAGES - 1 < iters)
            gemm_issue_stage(AgBase, BgBase, As, Bs,
                             it + STAGES - 1, (it + STAGES - 1) % STAGES, K, N,
                             aRow0, aRow1, aChunk0, bRow0, bRow1, bChunk0);
    }

    // epilogue
    #pragma unroll
    for (int mt = 0; mt < 4; mt++) {
        #pragma unroll
        for (int nt = 0; nt < 4; nt++) {
            int row0 = by * BM + wm + mt * 16 + group;
            int col0 = bx * BN + wn + nt * 8 + tig * 2;
            #pragma unroll
            for (int half = 0; half < 2; half++) {
                int row = row0 + half * 8;
                float v0 = acc[mt][nt][2 * half]     + bias[col0];
                float v1 = acc[mt][nt][2 * half + 1] + bias[col0 + 1];
                size_t idx = (size_t)row * N + col0;
                if (EPI == 0) {
                    *(bf162*)((bf16*)Cout + idx) = __floats2bfloat162_rn(v0, v1);
                } else if (EPI == 1) {
                    float2 r2 = *(const float2*)(res + idx);
                    *(float2*)((float*)Cout + idx) =
                        make_float2(r2.x + ls[col0] * v0,
                                    r2.y + ls[col0 + 1] * v1);
                } else {
                    float g0 = 0.5f * v0 * (1.0f + erff(v0 * 0.70710678118654752f));
                    float g1 = 0.5f * v1 * (1.0f + erff(v1 * 0.70710678118654752f));
                    *(bf162*)((bf16*)Cout + idx) = __floats2bfloat162_rn(g0, g1);
                }
            }
        }
    }
}

// ---------------- Attention (bf16 qkv in, bf16 out) ----------------
__global__ void attn_kernel(const bf16* __restrict__ qkv,
                            bf16* __restrict__ out,
                            int n, int token0)
{
    int qtiles = n >> 4;
    int b   = blockIdx.x;
    int qt  = b % qtiles;
    int r   = b / qtiles;
    int head = r % NH;
    int seq  = r / NH;
    size_t base = (size_t)(token0 + seq * n) * (3 * D);
    int ns = n + 4;

    extern __shared__ float sm[];
    float* Qs = sm;            // 16 x 64
    float* S  = sm + 16 * 64;  // 16 x ns

    int tid = threadIdx.x;
    int q0  = qt * 16;
    const float scale = 0.125f;

    for (int i = tid; i < 1024; i += 128) {
        int rq = i >> 6, c = i & 63;
        Qs[i] = __bfloat162float(
            qkv[base + (size_t)(q0 + rq) * (3 * D) + head * HD + c]) * scale;
    }
    __syncthreads();

    // pass A: S = Q . K
    for (int k = tid; k < n; k += 128) {
        const uint4* Kp = (const uint4*)(qkv + base + (size_t)k * (3 * D) + D + head * HD);
        float kr[64];
        #pragma unroll
        for (int c = 0; c < 8; c++) {
            uint4 raw = Kp[c];
            const bf162* h2 = (const bf162*)&raw;
            #pragma unroll
            for (int j = 0; j < 4; j++) {
                float2 f = __bfloat1622float2(h2[j]);
                kr[c * 8 + j * 2]     = f.x;
                kr[c * 8 + j * 2 + 1] = f.y;
            }
        }
        #pragma unroll
        for (int q = 0; q < 16; q++) {
            float s = 0.0f;
            #pragma unroll
            for (int c = 0; c < 64; c++) s += Qs[q * 64 + c] * kr[c];
            S[q * ns + k] = s;
        }
    }
    __syncthreads();

    // softmax per row
    int warp = tid >> 5, lane = tid & 31;
    for (int q = warp; q < 16; q += 4) {
        float* Sr = S + q * ns;
        float m = -1e30f;
        for (int k = lane; k < n; k += 32) m = fmaxf(m, Sr[k]);
        #pragma unroll
        for (int o = 16; o > 0; o >>= 1) m = fmaxf(m, __shfl_xor_sync(0xffffffffu, m, o));
        float l = 0.0f;
        for (int k = lane; k < n; k += 32) {
            float e = __expf(Sr[k] - m);
            Sr[k] = e; l += e;
        }
        #pragma unroll
        for (int o = 16; o > 0; o >>= 1) l += __shfl_xor_sync(0xffffffffu, l, o);
        float inv = 1.0f / l;
        for (int k = lane; k < n; k += 32) Sr[k] *= inv;
    }
    __syncthreads();

    // pass B: O = P @ V
    int q  = tid >> 3;
    int dg = (tid & 7) * 8;
    float acc[8] = {0, 0, 0, 0, 0, 0, 0, 0};
    const bf16* Vb = qkv + base + 2 * D + head * HD + dg;
    const float* Sr = S + q * ns;
    for (int k = 0; k < n; k++) {
        float p = Sr[k];
        uint4 raw = *(const uint4*)(Vb + (size_t)k * (3 * D));
        const bf162* h2 = (const bf162*)&raw;
        #pragma unroll
        for (int j = 0; j < 4; j++) {
            float2 f = __bfloat1622float2(h2[j]);
            acc[j * 2]     += p * f.x;
            acc[j * 2 + 1] += p * f.y;
        }
    }
    bf162 packed[4];
    #pragma unroll
    for (int j = 0; j < 4; j++)
        packed[j] = __floats2bfloat162_rn(acc[j * 2], acc[j * 2 + 1]);
    bf16* O = out + (size_t)(token0 + seq * n + q0 + q) * D + head * HD + dg;
    *(uint4*)O = *(uint4*)packed;
}

// ---------------- launch ----------------
extern "C" void kernel_launch(void* const* d_in, const int* in_sizes, int n_in,
                              void* d_out, int out_size)
{
    const float* x1     = (const float*)d_in[0];
    const float* x2     = (const float*)d_in[1];
    const float* ln1_g  = (const float*)d_in[2];
    const float* ln1_b  = (const float*)d_in[3];
    const float* w_qkv  = (const float*)d_in[4];
    const float* b_qkv  = (const float*)d_in[5];
    const float* w_proj = (const float*)d_in[6];
    const float* b_proj = (const float*)d_in[7];
    const float* ls1    = (const float*)d_in[8];
    const float* ln2_g  = (const float*)d_in[9];
    const float* ln2_b  = (const float*)d_in[10];
    const float* w_fc1  = (const float*)d_in[11];
    const float* b_fc1  = (const float*)d_in[12];
    const float* w_fc2  = (const float*)d_in[13];
    const float* b_fc2  = (const float*)d_in[14];
    const float* ls2    = (const float*)d_in[15];
    float* out = (float*)d_out;

    float *xbuf, *xmidbuf;
    bf16 *hbuf, *qkvbuf, *attbuf, *ffbuf, *wqkvh, *wprojh, *wfc1h, *wfc2h;
    cudaGetSymbolAddress((void**)&xbuf,   g_x);
    cudaGetSymbolAddress((void**)&xmidbuf,g_xmid);
    cudaGetSymbolAddress((void**)&hbuf,   g_h);
    cudaGetSymbolAddress((void**)&qkvbuf, g_qkvh);
    cudaGetSymbolAddress((void**)&attbuf, g_atth);
    cudaGetSymbolAddress((void**)&ffbuf,  g_ffh);
    cudaGetSymbolAddress((void**)&wqkvh,  g_wqkv);
    cudaGetSymbolAddress((void**)&wprojh, g_wproj);
    cudaGetSymbolAddress((void**)&wfc1h,  g_wfc1);
    cudaGetSymbolAddress((void**)&wfc2h,  g_wfc2);

    cudaFuncSetAttribute(gemm_bf16<0>, cudaFuncAttributeMaxDynamicSharedMemorySize, GEMM_SMEM);
    cudaFuncSetAttribute(gemm_bf16<1>, cudaFuncAttributeMaxDynamicSharedMemorySize, GEMM_SMEM);
    cudaFuncSetAttribute(gemm_bf16<2>, cudaFuncAttributeMaxDynamicSharedMemorySize, GEMM_SMEM);
    cudaFuncSetAttribute(attn_kernel, cudaFuncAttributeMaxDynamicSharedMemorySize,
                         (16 * (1024 + 4) + 1024) * 4);

    // 0. weights -> bf16
    cvt_kernel<<<512, 256>>>(w_qkv,  wqkvh,  D * 3 * D);
    cvt_kernel<<<256, 256>>>(w_proj, wprojh, D * D);
    cvt_kernel<<<512, 256>>>(w_fc1,  wfc1h,  D * FF_DIM);
    cvt_kernel<<<512, 256>>>(w_fc2,  wfc2h,  FF_DIM * D);

    // 1. gather + LN1 (bf16 h, fp32 residual copy)
    ln_kernel<<<NTOK, 256>>>(x1, x2, NTOK_A, ln1_g, ln1_b, hbuf, xbuf);

    // 2. QKV GEMM -> bf16
    gemm_bf16<0><<<dim3(2304 / BN, NTOK / BM), 256, GEMM_SMEM>>>(
        hbuf, wqkvh, b_qkv, nullptr, nullptr, qkvbuf, NTOK, 2304, D);

    // 3. attention
    attn_kernel<<<8 * NH * (512 / 16), 128, (16 * (512 + 4) + 1024) * 4>>>(
        qkvbuf, attbuf, 512, 0);
    attn_kernel<<<8 * NH * (1024 / 16), 128, (16 * (1024 + 4) + 1024) * 4>>>(
        qkvbuf, attbuf, 1024, NTOK_A);

    // 4. proj GEMM + layerscale + residual -> fp32 xmid
    gemm_bf16<1><<<dim3(768 / BN, NTOK / BM), 256, GEMM_SMEM>>>(
        attbuf, wprojh, b_proj, ls1, xbuf, xmidbuf, NTOK, D, D);

    // 5. LN2 -> bf16 h
    ln_kernel<<<NTOK, 256>>>(xmidbuf, xmidbuf, NTOK, ln2_g, ln2_b, hbuf, nullptr);

    // 6. FC1 GEMM + GELU -> bf16 ff
    gemm_bf16<2><<<dim3(FF_DIM / BN, NTOK / BM), 256, GEMM_SMEM>>>(
        hbuf, wfc1h, b_fc1, nullptr, nullptr, ffbuf, NTOK, FF_DIM, D);

    // 7. FC2 GEMM + layerscale + residual -> fp32 out
    gemm_bf16<1><<<dim3(768 / BN, NTOK / BM), 256, GEMM_SMEM>>>(
        ffbuf, wfc2h, b_fc2, ls2, xmidbuf, out, NTOK, D, FF_DIM);
}

// round 7
// speedup vs baseline: 5.4648x; 2.3006x over previous
#include <cuda_runtime.h>
#include <cuda_bf16.h>
#include <stdint.h>
#include <math.h>

#define D 768
#define NH 12
#define HD 64
#define FF_DIM 3072
#define NTOK 12288
#define NTOK_A 4096   // 8 seqs * 512

typedef __nv_bfloat16 bf16;
typedef __nv_bfloat162 bf162;

// ---------------- scratch ----------------
__device__ float g_x   [NTOK * D];                 // residual (fp32)
__device__ float g_xmid[NTOK * D];                 // post-attn residual (fp32)
__device__ bf16  g_h   [NTOK * D];                 // LN out (bf16)
__device__ bf16  g_qkvh[(size_t)NTOK * 3 * D];     // QKV (bf16)
__device__ bf16  g_atth[NTOK * D];                 // attention out (bf16)
__device__ bf16  g_ffh [(size_t)NTOK * FF_DIM];    // GELU out (bf16)
// bf16 weights
__device__ bf16  g_wqkv [D * 3 * D];
__device__ bf16  g_wproj[D * D];
__device__ bf16  g_wfc1 [D * FF_DIM];
__device__ bf16  g_wfc2 [FF_DIM * D];

// ---------------- fp32 -> bf16 convert ----------------
__global__ void cvt_kernel(const float* __restrict__ src, bf16* __restrict__ dst, int n)
{
    int i = (blockIdx.x * 256 + threadIdx.x) * 4;
    int stride = gridDim.x * 256 * 4;
    for (; i < n; i += stride) {
        float4 f = *(const float4*)(src + i);
        bf162 p0 = __floats2bfloat162_rn(f.x, f.y);
        bf162 p1 = __floats2bfloat162_rn(f.z, f.w);
        *(bf162*)(dst + i)     = p0;
        *(bf162*)(dst + i + 2) = p1;
    }
}

// ---------------- LayerNorm (fp32 in, bf16 out, optional fp32 copy) --------
__global__ void ln_kernel(const float* __restrict__ srcA,
                          const float* __restrict__ srcB,
                          int splitRow,
                          const float* __restrict__ gamma,
                          const float* __restrict__ beta,
                          bf16* __restrict__ out,
                          float* __restrict__ copy)
{
    int row = blockIdx.x;
    const float* src = (row < splitRow) ? srcA + (size_t)row * D
                                        : srcB + (size_t)(row - splitRow) * D;
    int t = threadIdx.x;
    float v0 = src[t], v1 = src[t + 256], v2 = src[t + 512];

    __shared__ float s1[256], s2[256];
    s1[t] = v0 + v1 + v2;
    s2[t] = v0 * v0 + v1 * v1 + v2 * v2;
    __syncthreads();
    for (int s = 128; s > 0; s >>= 1) {
        if (t < s) { s1[t] += s1[t + s]; s2[t] += s2[t + s]; }
        __syncthreads();
    }
    float m    = s1[0] * (1.0f / 768.0f);
    float var  = s2[0] * (1.0f / 768.0f) - m * m;
    float rstd = rsqrtf(var + 1e-5f);

    bf16* o = out + (size_t)row * D;
    o[t]       = __float2bfloat16((v0 - m) * rstd * gamma[t]       + beta[t]);
    o[t + 256] = __float2bfloat16((v1 - m) * rstd * gamma[t + 256] + beta[t + 256]);
    o[t + 512] = __float2bfloat16((v2 - m) * rstd * gamma[t + 512] + beta[t + 512]);
    if (copy) {
        float* c = copy + (size_t)row * D;
        c[t] = v0; c[t + 256] = v1; c[t + 512] = v2;
    }
}

// ---------------- common MMA helpers ----------------
__device__ __forceinline__ void cp_async16(unsigned saddr, const void* gptr) {
    asm volatile("cp.async.cg.shared.global [%0], [%1], 16;" :: "r"(saddr), "l"(gptr));
}
__device__ __forceinline__ void cp_commit() {
    asm volatile("cp.async.commit_group;");
}
template <int N>
__device__ __forceinline__ void cp_wait() {
    asm volatile("cp.async.wait_group %0;" :: "n"(N));
}
__device__ __forceinline__ void ldm_x4(unsigned saddr, unsigned* r) {
    asm volatile("ldmatrix.sync.aligned.m8n8.x4.shared.b16 {%0,%1,%2,%3}, [%4];"
                 : "=r"(r[0]), "=r"(r[1]), "=r"(r[2]), "=r"(r[3]) : "r"(saddr));
}
__device__ __forceinline__ void ldm_x4_trans(unsigned saddr, unsigned* r) {
    asm volatile("ldmatrix.sync.aligned.m8n8.x4.trans.shared.b16 {%0,%1,%2,%3}, [%4];"
                 : "=r"(r[0]), "=r"(r[1]), "=r"(r[2]), "=r"(r[3]) : "r"(saddr));
}
__device__ __forceinline__ void mma_bf16(float* c, const unsigned* a, const unsigned* b) {
    asm volatile(
        "mma.sync.aligned.m16n8k16.row.col.f32.bf16.bf16.f32 "
        "{%0,%1,%2,%3}, {%4,%5,%6,%7}, {%8,%9}, {%0,%1,%2,%3};"
        : "+f"(c[0]), "+f"(c[1]), "+f"(c[2]), "+f"(c[3])
        : "r"(a[0]), "r"(a[1]), "r"(a[2]), "r"(a[3]), "r"(b[0]), "r"(b[1]));
}
__device__ __forceinline__ unsigned pack2_bf16(float x, float y) {
    bf162 h = __floats2bfloat162_rn(x, y);
    return *reinterpret_cast<unsigned*>(&h);
}

// ---------------- bf16 tensor-core GEMM with cp.async (3 stages) -----------
#define BM 128
#define BN 128
#define BK 32
#define AST 40
#define BST 136
#define STAGES 3
#define A_STAGE (BM * AST)
#define B_STAGE (BK * BST)
#define GEMM_SMEM ((STAGES * (A_STAGE + B_STAGE)) * 2)

__device__ __forceinline__ void gemm_issue_stage(
    const bf16* AgBase, const bf16* BgBase, bf16* As, bf16* Bs,
    int kt, int s, int K, int N,
    int aRow0, int aRow1, int aChunk0, int bRow0, int bRow1, int bChunk0)
{
    const bf16* Ag = AgBase + kt * BK;
    bf16* Asb = As + s * A_STAGE;
    cp_async16((unsigned)__cvta_generic_to_shared(Asb + aRow0 * AST + aChunk0),
               Ag + (size_t)aRow0 * K + aChunk0);
    cp_async16((unsigned)__cvta_generic_to_shared(Asb + aRow1 * AST + aChunk0),
               Ag + (size_t)aRow1 * K + aChunk0);
    const bf16* Bg = BgBase + (size_t)(kt * BK) * N;
    bf16* Bsb = Bs + s * B_STAGE;
    cp_async16((unsigned)__cvta_generic_to_shared(Bsb + bRow0 * BST + bChunk0),
               Bg + (size_t)bRow0 * N + bChunk0);
    cp_async16((unsigned)__cvta_generic_to_shared(Bsb + bRow1 * BST + bChunk0),
               Bg + (size_t)bRow1 * N + bChunk0);
    cp_commit();
}

template <int EPI>
__global__ __launch_bounds__(256)
void gemm_bf16(const bf16* __restrict__ A, const bf16* __restrict__ B,
               const float* __restrict__ bias, const float* __restrict__ ls,
               const float* __restrict__ res, void* __restrict__ Cout,
               int M, int N, int K)
{
    extern __shared__ __align__(16) char smem_raw[];
    bf16* As = (bf16*)smem_raw;
    bf16* Bs = As + STAGES * A_STAGE;

    const int bx = blockIdx.x, by = blockIdx.y;
    const int tid = threadIdx.x;
    const int warp = tid >> 5, lane = tid & 31;
    const int wm = (warp >> 2) * 64;
    const int wn = (warp & 3) * 32;
    const int group = lane >> 2, tig = lane & 3;

    const int aRow0 = tid >> 2,  aChunk0 = (tid & 3) * 8;
    const int aRow1 = aRow0 + 64;
    const int bRow0 = tid >> 4,  bChunk0 = (tid & 15) * 8;
    const int bRow1 = bRow0 + 16;

    const bf16* AgBase = A + (size_t)(by * BM) * K;
    const bf16* BgBase = B + (size_t)(bx * BN);

    const int iters = K / BK;

    float acc[4][4][4];
    #pragma unroll
    for (int mt = 0; mt < 4; mt++)
        #pragma unroll
        for (int nt = 0; nt < 4; nt++) {
            acc[mt][nt][0] = 0.f; acc[mt][nt][1] = 0.f;
            acc[mt][nt][2] = 0.f; acc[mt][nt][3] = 0.f;
        }

    const int a_row = wm + (lane & 15);
    const int a_col = (lane >> 4) * 8;
    const int b_krow = ((lane >> 3) & 1) * 8 + (lane & 7);
    const int b_ncol = wn + (lane >> 4) * 8;

    gemm_issue_stage(AgBase, BgBase, As, Bs, 0, 0, K, N,
                     aRow0, aRow1, aChunk0, bRow0, bRow1, bChunk0);
    gemm_issue_stage(AgBase, BgBase, As, Bs, 1, 1, K, N,
                     aRow0, aRow1, aChunk0, bRow0, bRow1, bChunk0);

    for (int it = 0; it < iters; it++) {
        cp_wait<STAGES - 2>();
        __syncthreads();

        const int s = it % STAGES;
        unsigned As_base = (unsigned)__cvta_generic_to_shared(As + s * A_STAGE);
        unsigned Bs_base = (unsigned)__cvta_generic_to_shared(Bs + s * B_STAGE);

        #pragma unroll
        for (int kstep = 0; kstep < 2; kstep++) {
            const int k0 = kstep * 16;
            unsigned afr[4][4];
            unsigned bfr[4][2];
            #pragma unroll
            for (int mt = 0; mt < 4; mt++) {
                unsigned ad = As_base +
                    (unsigned)(((a_row + mt * 16) * AST + k0 + a_col) * 2);
                ldm_x4(ad, afr[mt]);
            }
            #pragma unroll
            for (int np = 0; np < 2; np++) {
                unsigned bd = Bs_base +
                    (unsigned)(((k0 + b_krow) * BST + b_ncol + np * 16) * 2);
                unsigned rr[4];
                ldm_x4_trans(bd, rr);
                bfr[2 * np][0] = rr[0]; bfr[2 * np][1] = rr[1];
                bfr[2 * np + 1][0] = rr[2]; bfr[2 * np + 1][1] = rr[3];
            }
            #pragma unroll
            for (int mt = 0; mt < 4; mt++)
                #pragma unroll
                for (int nt = 0; nt < 4; nt++)
                    mma_bf16(acc[mt][nt], afr[mt], bfr[nt]);
        }

        __syncthreads();
        if (it + STAGES - 1 < iters)
            gemm_issue_stage(AgBase, BgBase, As, Bs,
                             it + STAGES - 1, (it + STAGES - 1) % STAGES, K, N,
                             aRow0, aRow1, aChunk0, bRow0, bRow1, bChunk0);
    }

    #pragma unroll
    for (int mt = 0; mt < 4; mt++) {
        #pragma unroll
        for (int nt = 0; nt < 4; nt++) {
            int row0 = by * BM + wm + mt * 16 + group;
            int col0 = bx * BN + wn + nt * 8 + tig * 2;
            #pragma unroll
            for (int half = 0; half < 2; half++) {
                int row = row0 + half * 8;
                float v0 = acc[mt][nt][2 * half]     + bias[col0];
                float v1 = acc[mt][nt][2 * half + 1] + bias[col0 + 1];
                size_t idx = (size_t)row * N + col0;
                if (EPI == 0) {
                    *(bf162*)((bf16*)Cout + idx) = __floats2bfloat162_rn(v0, v1);
                } else if (EPI == 1) {
                    float2 r2 = *(const float2*)(res + idx);
                    *(float2*)((float*)Cout + idx) =
                        make_float2(r2.x + ls[col0] * v0,
                                    r2.y + ls[col0 + 1] * v1);
                } else {
                    float g0 = 0.5f * v0 * (1.0f + erff(v0 * 0.70710678118654752f));
                    float g1 = 0.5f * v1 * (1.0f + erff(v1 * 0.70710678118654752f));
                    *(bf162*)((bf16*)Cout + idx) = __floats2bfloat162_rn(g0, g1);
                }
            }
        }
    }
}

// ---------------- Flash attention (bf16 tensor cores) ----------------
// Block = (seq, head, 64-query tile), 128 threads (4 warps, 16 q-rows each).
// K/V iterated in 64-key tiles via smem (stride 72 bf16 = conflict-free).
#define FA_QT 64
#define FA_KT 64
#define FA_ST 72   // smem row stride in bf16

__global__ __launch_bounds__(128)
void fattn_kernel(const bf16* __restrict__ qkv,
                  bf16* __restrict__ out,
                  int n, int token0)
{
    const int qtiles = n / FA_QT;
    int b    = blockIdx.x;
    int qt   = b % qtiles;
    int r    = b / qtiles;
    int head = r % NH;
    int seq  = r / NH;
    const size_t base = (size_t)(token0 + seq * n) * (3 * D);
    const int q0 = qt * FA_QT;

    __shared__ __align__(16) bf16 Qs[FA_QT * FA_ST];
    __shared__ __align__(16) bf16 Ks[FA_KT * FA_ST];
    __shared__ __align__(16) bf16 Vs[FA_KT * FA_ST];

    const int tid  = threadIdx.x;
    const int warp = tid >> 5, lane = tid & 31;
    const int g = lane >> 2, t = lane & 3;

    // ---- load Q tile (scaled by 2^-3, exact in bf16) ----
    const bf162 sc = __float2bfloat162_rn(0.125f);
    for (int i = tid; i < FA_QT * 8; i += 128) {
        int row = i >> 3, c = (i & 7) * 8;
        uint4 v = *(const uint4*)(qkv + base + (size_t)(q0 + row) * (3 * D) + head * HD + c);
        bf162* p = (bf162*)&v;
        #pragma unroll
        for (int j = 0; j < 4; j++) p[j] = __hmul2(p[j], sc);
        *(uint4*)(&Qs[row * FA_ST + c]) = v;
    }
    __syncthreads();

    // ---- Q fragments (held for whole block) ----
    unsigned Qbase = (unsigned)__cvta_generic_to_shared(Qs);
    unsigned Kbase = (unsigned)__cvta_generic_to_shared(Ks);
    unsigned Vbase = (unsigned)__cvta_generic_to_shared(Vs);
    const int arow  = warp * 16 + (lane & 15);
    const int acol  = (lane >> 4) * 8;
    const int bkrow = ((lane >> 3) & 1) * 8 + (lane & 7);
    const int bncol = (lane >> 4) * 8;

    unsigned qf[4][4];
    #pragma unroll
    for (int dc = 0; dc < 4; dc++)
        ldm_x4(Qbase + (unsigned)((arow * FA_ST + dc * 16 + acol) * 2), qf[dc]);

    float m_i[2] = {-1e30f, -1e30f};
    float l_i[2] = {0.f, 0.f};
    float o[8][4];
    #pragma unroll
    for (int nt = 0; nt < 8; nt++) {
        o[nt][0] = 0.f; o[nt][1] = 0.f; o[nt][2] = 0.f; o[nt][3] = 0.f;
    }

    const int ktiles = n / FA_KT;
    for (int kt = 0; kt < ktiles; kt++) {
        __syncthreads();
        // load K/V tile
        for (int i = tid; i < FA_KT * 8; i += 128) {
            int row = i >> 3, c = (i & 7) * 8;
            const bf16* src = qkv + base + (size_t)(kt * FA_KT + row) * (3 * D) + head * HD + c;
            *(uint4*)(&Ks[row * FA_ST + c]) = *(const uint4*)(src + D);
            *(uint4*)(&Vs[row * FA_ST + c]) = *(const uint4*)(src + 2 * D);
        }
        __syncthreads();

        // ---- S = Q K^T ----
        float s[8][4];
        #pragma unroll
        for (int nt = 0; nt < 8; nt++) {
            s[nt][0] = 0.f; s[nt][1] = 0.f; s[nt][2] = 0.f; s[nt][3] = 0.f;
        }
        #pragma unroll
        for (int dc = 0; dc < 4; dc++) {
            #pragma unroll
            for (int ng = 0; ng < 4; ng++) {   // 16-key groups
                unsigned kf[4];
                ldm_x4(Kbase + (unsigned)(((ng * 16 + (lane & 15)) * FA_ST + dc * 16 + acol) * 2), kf);
                unsigned b0[2] = {kf[0], kf[2]};   // keys 0-7 of group
                unsigned b1[2] = {kf[1], kf[3]};   // keys 8-15
                mma_bf16(s[2 * ng],     qf[dc], b0);
                mma_bf16(s[2 * ng + 1], qf[dc], b1);
            }
        }

        // ---- online softmax ----
        float rmax0 = -1e30f, rmax1 = -1e30f;
        #pragma unroll
        for (int nt = 0; nt < 8; nt++) {
            rmax0 = fmaxf(rmax0, fmaxf(s[nt][0], s[nt][1]));
            rmax1 = fmaxf(rmax1, fmaxf(s[nt][2], s[nt][3]));
        }
        rmax0 = fmaxf(rmax0, __shfl_xor_sync(0xffffffffu, rmax0, 1));
        rmax0 = fmaxf(rmax0, __shfl_xor_sync(0xffffffffu, rmax0, 2));
        rmax1 = fmaxf(rmax1, __shfl_xor_sync(0xffffffffu, rmax1, 1));
        rmax1 = fmaxf(rmax1, __shfl_xor_sync(0xffffffffu, rmax1, 2));

        float mn0 = fmaxf(m_i[0], rmax0);
        float mn1 = fmaxf(m_i[1], rmax1);
        float c0 = __expf(m_i[0] - mn0);
        float c1 = __expf(m_i[1] - mn1);
        m_i[0] = mn0; m_i[1] = mn1;

        float rs0 = 0.f, rs1 = 0.f;
        #pragma unroll
        for (int nt = 0; nt < 8; nt++) {
            s[nt][0] = __expf(s[nt][0] - mn0);
            s[nt][1] = __expf(s[nt][1] - mn0);
            s[nt][2] = __expf(s[nt][2] - mn1);
            s[nt][3] = __expf(s[nt][3] - mn1);
            rs0 += s[nt][0] + s[nt][1];
            rs1 += s[nt][2] + s[nt][3];
        }
        rs0 += __shfl_xor_sync(0xffffffffu, rs0, 1);
        rs0 += __shfl_xor_sync(0xffffffffu, rs0, 2);
        rs1 += __shfl_xor_sync(0xffffffffu, rs1, 1);
        rs1 += __shfl_xor_sync(0xffffffffu, rs1, 2);
        l_i[0] = l_i[0] * c0 + rs0;
        l_i[1] = l_i[1] * c1 + rs1;

        #pragma unroll
        for (int nt = 0; nt < 8; nt++) {
            o[nt][0] *= c0; o[nt][1] *= c0;
            o[nt][2] *= c1; o[nt][3] *= c1;
        }

        // ---- O += P V  (P from S accumulators, no smem round-trip) ----
        #pragma unroll
        for (int kc = 0; kc < 4; kc++) {   // 16-key chunks
            unsigned pa[4];
            pa[0] = pack2_bf16(s[2 * kc][0],     s[2 * kc][1]);
            pa[1] = pack2_bf16(s[2 * kc][2],     s[2 * kc][3]);
            pa[2] = pack2_bf16(s[2 * kc + 1][0], s[2 * kc + 1][1]);
            pa[3] = pack2_bf16(s[2 * kc + 1][2], s[2 * kc + 1][3]);
            #pragma unroll
            for (int dp = 0; dp < 4; dp++) {   // d 16-col pairs
                unsigned rr[4];
                ldm_x4_trans(Vbase +
                    (unsigned)(((kc * 16 + bkrow) * FA_ST + dp * 16 + bncol) * 2), rr);
                unsigned vb0[2] = {rr[0], rr[1]};
                unsigned vb1[2] = {rr[2], rr[3]};
                mma_bf16(o[2 * dp],     pa, vb0);
                mma_bf16(o[2 * dp + 1], pa, vb1);
            }
        }
    }

    // ---- epilogue: O / l, write bf16 ----
    float inv0 = 1.0f / l_i[0];
    float inv1 = 1.0f / l_i[1];
    int row0 = token0 + seq * n + q0 + warp * 16 + g;
    #pragma unroll
    for (int nt = 0; nt < 8; nt++) {
        int col = head * HD + nt * 8 + 2 * t;
        *(bf162*)(out + (size_t)row0 * D + col) =
            __floats2bfloat162_rn(o[nt][0] * inv0, o[nt][1] * inv0);
        *(bf162*)(out + (size_t)(row0 + 8) * D + col) =
            __floats2bfloat162_rn(o[nt][2] * inv1, o[nt][3] * inv1);
    }
}

// ---------------- launch ----------------
extern "C" void kernel_launch(void* const* d_in, const int* in_sizes, int n_in,
                              void* d_out, int out_size)
{
    const float* x1     = (const float*)d_in[0];
    const float* x2     = (const float*)d_in[1];
    const float* ln1_g  = (const float*)d_in[2];
    const float* ln1_b  = (const float*)d_in[3];
    const float* w_qkv  = (const float*)d_in[4];
    const float* b_qkv  = (const float*)d_in[5];
    const float* w_proj = (const float*)d_in[6];
    const float* b_proj = (const float*)d_in[7];
    const float* ls1    = (const float*)d_in[8];
    const float* ln2_g  = (const float*)d_in[9];
    const float* ln2_b  = (const float*)d_in[10];
    const float* w_fc1  = (const float*)d_in[11];
    const float* b_fc1  = (const float*)d_in[12];
    const float* w_fc2  = (const float*)d_in[13];
    const float* b_fc2  = (const float*)d_in[14];
    const float* ls2    = (const float*)d_in[15];
    float* out = (float*)d_out;

    float *xbuf, *xmidbuf;
    bf16 *hbuf, *qkvbuf, *attbuf, *ffbuf, *wqkvh, *wprojh, *wfc1h, *wfc2h;
    cudaGetSymbolAddress((void**)&xbuf,   g_x);
    cudaGetSymbolAddress((void**)&xmidbuf,g_xmid);
    cudaGetSymbolAddress((void**)&hbuf,   g_h);
    cudaGetSymbolAddress((void**)&qkvbuf, g_qkvh);
    cudaGetSymbolAddress((void**)&attbuf, g_atth);
    cudaGetSymbolAddress((void**)&ffbuf,  g_ffh);
    cudaGetSymbolAddress((void**)&wqkvh,  g_wqkv);
    cudaGetSymbolAddress((void**)&wprojh, g_wproj);
    cudaGetSymbolAddress((void**)&wfc1h,  g_wfc1);
    cudaGetSymbolAddress((void**)&wfc2h,  g_wfc2);

    cudaFuncSetAttribute(gemm_bf16<0>, cudaFuncAttributeMaxDynamicSharedMemorySize, GEMM_SMEM);
    cudaFuncSetAttribute(gemm_bf16<1>, cudaFuncAttributeMaxDynamicSharedMemorySize, GEMM_SMEM);
    cudaFuncSetAttribute(gemm_bf16<2>, cudaFuncAttributeMaxDynamicSharedMemorySize, GEMM_SMEM);

    // 0. weights -> bf16
    cvt_kernel<<<512, 256>>>(w_qkv,  wqkvh,  D * 3 * D);
    cvt_kernel<<<256, 256>>>(w_proj, wprojh, D * D);
    cvt_kernel<<<512, 256>>>(w_fc1,  wfc1h,  D * FF_DIM);
    cvt_kernel<<<512, 256>>>(w_fc2,  wfc2h,  FF_DIM * D);

    // 1. gather + LN1 (bf16 h, fp32 residual copy)
    ln_kernel<<<NTOK, 256>>>(x1, x2, NTOK_A, ln1_g, ln1_b, hbuf, xbuf);

    // 2. QKV GEMM -> bf16
    gemm_bf16<0><<<dim3(2304 / BN, NTOK / BM), 256, GEMM_SMEM>>>(
        hbuf, wqkvh, b_qkv, nullptr, nullptr, qkvbuf, NTOK, 2304, D);

    // 3. flash attention
    fattn_kernel<<<8 * NH * (512 / FA_QT), 128>>>(qkvbuf, attbuf, 512, 0);
    fattn_kernel<<<8 * NH * (1024 / FA_QT), 128>>>(qkvbuf, attbuf, 1024, NTOK_A);

    // 4. proj GEMM + layerscale + residual -> fp32 xmid
    gemm_bf16<1><<<dim3(768 / BN, NTOK / BM), 256, GEMM_SMEM>>>(
        attbuf, wprojh, b_proj, ls1, xbuf, xmidbuf, NTOK, D, D);

    // 5. LN2 -> bf16 h
    ln_kernel<<<NTOK, 256>>>(xmidbuf, xmidbuf, NTOK, ln2_g, ln2_b, hbuf, nullptr);

    // 6. FC1 GEMM + GELU -> bf16 ff
    gemm_bf16<2><<<dim3(FF_DIM / BN, NTOK / BM), 256, GEMM_SMEM>>>(
        hbuf, wfc1h, b_fc1, nullptr, nullptr, ffbuf, NTOK, FF_DIM, D);

    // 7. FC2 GEMM + layerscale + residual -> fp32 out
    gemm_bf16<1><<<dim3(768 / BN, NTOK / BM), 256, GEMM_SMEM>>>(
        ffbuf, wfc2h, b_fc2, ls2, xmidbuf, out, NTOK, D, FF_DIM);
}

// round 8
// speedup vs baseline: 5.7594x; 1.0539x over previous
#include <cuda_runtime.h>
#include <cuda_bf16.h>
#include <stdint.h>
#include <math.h>

#define D 768
#define NH 12
#define HD 64
#define FF_DIM 3072
#define NTOK 12288
#define NTOK_A 4096   // 8 seqs * 512

typedef __nv_bfloat16 bf16;
typedef __nv_bfloat162 bf162;

// ---------------- scratch ----------------
__device__ float g_x   [NTOK * D];                 // residual (fp32)
__device__ float g_xmid[NTOK * D];                 // post-attn residual (fp32)
__device__ bf16  g_h   [NTOK * D];                 // LN out (bf16)
__device__ bf16  g_qkvh[(size_t)NTOK * 3 * D];     // QKV (bf16)
__device__ bf16  g_atth[NTOK * D];                 // attention out (bf16)
__device__ bf16  g_ffh [(size_t)NTOK * FF_DIM];    // GELU out (bf16)
// bf16 weights
__device__ bf16  g_wqkv [D * 3 * D];
__device__ bf16  g_wproj[D * D];
__device__ bf16  g_wfc1 [D * FF_DIM];
__device__ bf16  g_wfc2 [FF_DIM * D];

// ---------------- fp32 -> bf16 convert ----------------
__global__ void cvt_kernel(const float* __restrict__ src, bf16* __restrict__ dst, int n)
{
    int i = (blockIdx.x * 256 + threadIdx.x) * 4;
    int stride = gridDim.x * 256 * 4;
    for (; i < n; i += stride) {
        float4 f = *(const float4*)(src + i);
        bf162 p0 = __floats2bfloat162_rn(f.x, f.y);
        bf162 p1 = __floats2bfloat162_rn(f.z, f.w);
        *(bf162*)(dst + i)     = p0;
        *(bf162*)(dst + i + 2) = p1;
    }
}

// ---------------- LayerNorm (fp32 in, bf16 out, optional fp32 copy) --------
__global__ void ln_kernel(const float* __restrict__ srcA,
                          const float* __restrict__ srcB,
                          int splitRow,
                          const float* __restrict__ gamma,
                          const float* __restrict__ beta,
                          bf16* __restrict__ out,
                          float* __restrict__ copy)
{
    int row = blockIdx.x;
    const float* src = (row < splitRow) ? srcA + (size_t)row * D
                                        : srcB + (size_t)(row - splitRow) * D;
    int t = threadIdx.x;
    float v0 = src[t], v1 = src[t + 256], v2 = src[t + 512];

    __shared__ float s1[256], s2[256];
    s1[t] = v0 + v1 + v2;
    s2[t] = v0 * v0 + v1 * v1 + v2 * v2;
    __syncthreads();
    for (int s = 128; s > 0; s >>= 1) {
        if (t < s) { s1[t] += s1[t + s]; s2[t] += s2[t + s]; }
        __syncthreads();
    }
    float m    = s1[0] * (1.0f / 768.0f);
    float var  = s2[0] * (1.0f / 768.0f) - m * m;
    float rstd = rsqrtf(var + 1e-5f);

    bf16* o = out + (size_t)row * D;
    o[t]       = __float2bfloat16((v0 - m) * rstd * gamma[t]       + beta[t]);
    o[t + 256] = __float2bfloat16((v1 - m) * rstd * gamma[t + 256] + beta[t + 256]);
    o[t + 512] = __float2bfloat16((v2 - m) * rstd * gamma[t + 512] + beta[t + 512]);
    if (copy) {
        float* c = copy + (size_t)row * D;
        c[t] = v0; c[t + 256] = v1; c[t + 512] = v2;
    }
}

// ---------------- common MMA helpers ----------------
__device__ __forceinline__ void cp_async16(unsigned saddr, const void* gptr) {
    asm volatile("cp.async.cg.shared.global [%0], [%1], 16;" :: "r"(saddr), "l"(gptr));
}
__device__ __forceinline__ void cp_commit() {
    asm volatile("cp.async.commit_group;");
}
template <int N>
__device__ __forceinline__ void cp_wait() {
    asm volatile("cp.async.wait_group %0;" :: "n"(N));
}
__device__ __forceinline__ void ldm_x4(unsigned saddr, unsigned* r) {
    asm volatile("ldmatrix.sync.aligned.m8n8.x4.shared.b16 {%0,%1,%2,%3}, [%4];"
                 : "=r"(r[0]), "=r"(r[1]), "=r"(r[2]), "=r"(r[3]) : "r"(saddr));
}
__device__ __forceinline__ void ldm_x4_trans(unsigned saddr, unsigned* r) {
    asm volatile("ldmatrix.sync.aligned.m8n8.x4.trans.shared.b16 {%0,%1,%2,%3}, [%4];"
                 : "=r"(r[0]), "=r"(r[1]), "=r"(r[2]), "=r"(r[3]) : "r"(saddr));
}
__device__ __forceinline__ void mma_bf16(float* c, const unsigned* a, const unsigned* b) {
    asm volatile(
        "mma.sync.aligned.m16n8k16.row.col.f32.bf16.bf16.f32 "
        "{%0,%1,%2,%3}, {%4,%5,%6,%7}, {%8,%9}, {%0,%1,%2,%3};"
        : "+f"(c[0]), "+f"(c[1]), "+f"(c[2]), "+f"(c[3])
        : "r"(a[0]), "r"(a[1]), "r"(a[2]), "r"(a[3]), "r"(b[0]), "r"(b[1]));
}
__device__ __forceinline__ unsigned pack2_bf16(float x, float y) {
    bf162 h = __floats2bfloat162_rn(x, y);
    return *reinterpret_cast<unsigned*>(&h);
}

// ---------------- bf16 tensor-core GEMM, cp.async 3-stage, BK=64 ----------
#define BM 128
#define BN 128
#define BK 64
#define AST 72     // As row stride (bf16): 144B -> +4 banks/row
#define BST 136    // Bs row stride (bf16): 272B -> +4 banks/row
#define STAGES 3
#define A_STAGE (BM * AST)             // 9216 bf16
#define B_STAGE (BK * BST)             // 8704 bf16
#define GEMM_SMEM ((STAGES * (A_STAGE + B_STAGE)) * 2)   // 107520 B

// stage issue: A 128x64, B 64x128, 4 cp.async of 16B per matrix per thread
__device__ __forceinline__ void gemm_issue_stage(
    const bf16* AgBase, const bf16* BgBase, bf16* As, bf16* Bs,
    int kt, int s, int K, int N,
    int aRow, int aCol, int bRow, int bCol)
{
    const bf16* Ag = AgBase + kt * BK;
    bf16* Asb = As + s * A_STAGE;
    #pragma unroll
    for (int i = 0; i < 4; i++) {
        int row = aRow + 32 * i;
        cp_async16((unsigned)__cvta_generic_to_shared(Asb + row * AST + aCol),
                   Ag + (size_t)row * K + aCol);
    }
    const bf16* Bg = BgBase + (size_t)(kt * BK) * N;
    bf16* Bsb = Bs + s * B_STAGE;
    #pragma unroll
    for (int i = 0; i < 4; i++) {
        int row = bRow + 16 * i;
        cp_async16((unsigned)__cvta_generic_to_shared(Bsb + row * BST + bCol),
                   Bg + (size_t)row * N + bCol);
    }
    cp_commit();
}

template <int EPI>
__global__ __launch_bounds__(256)
void gemm_bf16(const bf16* __restrict__ A, const bf16* __restrict__ B,
               const float* __restrict__ bias, const float* __restrict__ ls,
               const float* __restrict__ res, void* __restrict__ Cout,
               int M, int N, int K)
{
    extern __shared__ __align__(16) char smem_raw[];
    bf16* As = (bf16*)smem_raw;
    bf16* Bs = As + STAGES * A_STAGE;

    const int bx = blockIdx.x, by = blockIdx.y;
    const int tid = threadIdx.x;
    const int warp = tid >> 5, lane = tid & 31;
    const int wm = (warp >> 2) * 64;
    const int wn = (warp & 3) * 32;
    const int group = lane >> 2, tig = lane & 3;

    // staging layout (BK=64)
    const int aRow = tid >> 3, aCol = (tid & 7) * 8;    // 32 rows x 8 chunks
    const int bRow = tid >> 4, bCol = (tid & 15) * 8;   // 16 rows x 16 chunks

    const bf16* AgBase = A + (size_t)(by * BM) * K;
    const bf16* BgBase = B + (size_t)(bx * BN);

    const int iters = K / BK;

    float acc[4][4][4];
    #pragma unroll
    for (int mt = 0; mt < 4; mt++)
        #pragma unroll
        for (int nt = 0; nt < 4; nt++) {
            acc[mt][nt][0] = 0.f; acc[mt][nt][1] = 0.f;
            acc[mt][nt][2] = 0.f; acc[mt][nt][3] = 0.f;
        }

    const int a_row = wm + (lane & 15);
    const int a_col = (lane >> 4) * 8;
    const int b_krow = ((lane >> 3) & 1) * 8 + (lane & 7);
    const int b_ncol = wn + (lane >> 4) * 8;

    gemm_issue_stage(AgBase, BgBase, As, Bs, 0, 0, K, N, aRow, aCol, bRow, bCol);
    gemm_issue_stage(AgBase, BgBase, As, Bs, 1, 1, K, N, aRow, aCol, bRow, bCol);

    for (int it = 0; it < iters; it++) {
        cp_wait<STAGES - 2>();
        __syncthreads();

        // issue into stage consumed two iterations ago (safe after barrier)
        if (it + 2 < iters)
            gemm_issue_stage(AgBase, BgBase, As, Bs,
                             it + 2, (it + 2) % STAGES, K, N,
                             aRow, aCol, bRow, bCol);

        const int s = it % STAGES;
        unsigned As_base = (unsigned)__cvta_generic_to_shared(As + s * A_STAGE);
        unsigned Bs_base = (unsigned)__cvta_generic_to_shared(Bs + s * B_STAGE);

        #pragma unroll
        for (int kstep = 0; kstep < 4; kstep++) {
            const int k0 = kstep * 16;
            unsigned afr[4][4];
            unsigned bfr[4][2];
            #pragma unroll
            for (int mt = 0; mt < 4; mt++) {
                unsigned ad = As_base +
                    (unsigned)(((a_row + mt * 16) * AST + k0 + a_col) * 2);
                ldm_x4(ad, afr[mt]);
            }
            #pragma unroll
            for (int np = 0; np < 2; np++) {
                unsigned bd = Bs_base +
                    (unsigned)(((k0 + b_krow) * BST + b_ncol + np * 16) * 2);
                unsigned rr[4];
                ldm_x4_trans(bd, rr);
                bfr[2 * np][0] = rr[0]; bfr[2 * np][1] = rr[1];
                bfr[2 * np + 1][0] = rr[2]; bfr[2 * np + 1][1] = rr[3];
            }
            #pragma unroll
            for (int mt = 0; mt < 4; mt++)
                #pragma unroll
                for (int nt = 0; nt < 4; nt++)
                    mma_bf16(acc[mt][nt], afr[mt], bfr[nt]);
        }
    }

    #pragma unroll
    for (int mt = 0; mt < 4; mt++) {
        #pragma unroll
        for (int nt = 0; nt < 4; nt++) {
            int row0 = by * BM + wm + mt * 16 + group;
            int col0 = bx * BN + wn + nt * 8 + tig * 2;
            #pragma unroll
            for (int half = 0; half < 2; half++) {
                int row = row0 + half * 8;
                float v0 = acc[mt][nt][2 * half]     + bias[col0];
                float v1 = acc[mt][nt][2 * half + 1] + bias[col0 + 1];
                size_t idx = (size_t)row * N + col0;
                if (EPI == 0) {
                    *(bf162*)((bf16*)Cout + idx) = __floats2bfloat162_rn(v0, v1);
                } else if (EPI == 1) {
                    float2 r2 = *(const float2*)(res + idx);
                    *(float2*)((float*)Cout + idx) =
                        make_float2(r2.x + ls[col0] * v0,
                                    r2.y + ls[col0 + 1] * v1);
                } else {
                    float g0 = 0.5f * v0 * (1.0f + erff(v0 * 0.70710678118654752f));
                    float g1 = 0.5f * v1 * (1.0f + erff(v1 * 0.70710678118654752f));
                    *(bf162*)((bf16*)Cout + idx) = __floats2bfloat162_rn(g0, g1);
                }
            }
        }
    }
}

// ---------------- Flash attention (bf16 tensor cores) ----------------
#define FA_QT 64
#define FA_KT 64
#define FA_ST 72

__global__ __launch_bounds__(128)
void fattn_kernel(const bf16* __restrict__ qkv,
                  bf16* __restrict__ out,
                  int n, int token0)
{
    const int qtiles = n / FA_QT;
    int b    = blockIdx.x;
    int qt   = b % qtiles;
    int r    = b / qtiles;
    int head = r % NH;
    int seq  = r / NH;
    const size_t base = (size_t)(token0 + seq * n) * (3 * D);
    const int q0 = qt * FA_QT;

    __shared__ __align__(16) bf16 Qs[FA_QT * FA_ST];
    __shared__ __align__(16) bf16 Ks[FA_KT * FA_ST];
    __shared__ __align__(16) bf16 Vs[FA_KT * FA_ST];

    const int tid  = threadIdx.x;
    const int warp = tid >> 5, lane = tid & 31;
    const int g = lane >> 2, t = lane & 3;

    const bf162 sc = __float2bfloat162_rn(0.125f);
    for (int i = tid; i < FA_QT * 8; i += 128) {
        int row = i >> 3, c = (i & 7) * 8;
        uint4 v = *(const uint4*)(qkv + base + (size_t)(q0 + row) * (3 * D) + head * HD + c);
        bf162* p = (bf162*)&v;
        #pragma unroll
        for (int j = 0; j < 4; j++) p[j] = __hmul2(p[j], sc);
        *(uint4*)(&Qs[row * FA_ST + c]) = v;
    }
    __syncthreads();

    unsigned Qbase = (unsigned)__cvta_generic_to_shared(Qs);
    unsigned Kbase = (unsigned)__cvta_generic_to_shared(Ks);
    unsigned Vbase = (unsigned)__cvta_generic_to_shared(Vs);
    const int arow  = warp * 16 + (lane & 15);
    const int acol  = (lane >> 4) * 8;
    const int bkrow = ((lane >> 3) & 1) * 8 + (lane & 7);
    const int bncol = (lane >> 4) * 8;

    unsigned qf[4][4];
    #pragma unroll
    for (int dc = 0; dc < 4; dc++)
        ldm_x4(Qbase + (unsigned)((arow * FA_ST + dc * 16 + acol) * 2), qf[dc]);

    float m_i[2] = {-1e30f, -1e30f};
    float l_i[2] = {0.f, 0.f};
    float o[8][4];
    #pragma unroll
    for (int nt = 0; nt < 8; nt++) {
        o[nt][0] = 0.f; o[nt][1] = 0.f; o[nt][2] = 0.f; o[nt][3] = 0.f;
    }

    const int ktiles = n / FA_KT;
    for (int kt = 0; kt < ktiles; kt++) {
        __syncthreads();
        for (int i = tid; i < FA_KT * 8; i += 128) {
            int row = i >> 3, c = (i & 7) * 8;
            const bf16* src = qkv + base + (size_t)(kt * FA_KT + row) * (3 * D) + head * HD + c;
            *(uint4*)(&Ks[row * FA_ST + c]) = *(const uint4*)(src + D);
            *(uint4*)(&Vs[row * FA_ST + c]) = *(const uint4*)(src + 2 * D);
        }
        __syncthreads();

        float s[8][4];
        #pragma unroll
        for (int nt = 0; nt < 8; nt++) {
            s[nt][0] = 0.f; s[nt][1] = 0.f; s[nt][2] = 0.f; s[nt][3] = 0.f;
        }
        #pragma unroll
        for (int dc = 0; dc < 4; dc++) {
            #pragma unroll
            for (int ng = 0; ng < 4; ng++) {
                unsigned kf[4];
                ldm_x4(Kbase + (unsigned)(((ng * 16 + (lane & 15)) * FA_ST + dc * 16 + acol) * 2), kf);
                unsigned b0[2] = {kf[0], kf[2]};
                unsigned b1[2] = {kf[1], kf[3]};
                mma_bf16(s[2 * ng],     qf[dc], b0);
                mma_bf16(s[2 * ng + 1], qf[dc], b1);
            }
        }

        float rmax0 = -1e30f, rmax1 = -1e30f;
        #pragma unroll
        for (int nt = 0; nt < 8; nt++) {
            rmax0 = fmaxf(rmax0, fmaxf(s[nt][0], s[nt][1]));
            rmax1 = fmaxf(rmax1, fmaxf(s[nt][2], s[nt][3]));
        }
        rmax0 = fmaxf(rmax0, __shfl_xor_sync(0xffffffffu, rmax0, 1));
        rmax0 = fmaxf(rmax0, __shfl_xor_sync(0xffffffffu, rmax0, 2));
        rmax1 = fmaxf(rmax1, __shfl_xor_sync(0xffffffffu, rmax1, 1));
        rmax1 = fmaxf(rmax1, __shfl_xor_sync(0xffffffffu, rmax1, 2));

        float mn0 = fmaxf(m_i[0], rmax0);
        float mn1 = fmaxf(m_i[1], rmax1);
        float c0 = __expf(m_i[0] - mn0);
        float c1 = __expf(m_i[1] - mn1);
        m_i[0] = mn0; m_i[1] = mn1;

        float rs0 = 0.f, rs1 = 0.f;
        #pragma unroll
        for (int nt = 0; nt < 8; nt++) {
            s[nt][0] = __expf(s[nt][0] - mn0);
            s[nt][1] = __expf(s[nt][1] - mn0);
            s[nt][2] = __expf(s[nt][2] - mn1);
            s[nt][3] = __expf(s[nt][3] - mn1);
            rs0 += s[nt][0] + s[nt][1];
            rs1 += s[nt][2] + s[nt][3];
        }
        rs0 += __shfl_xor_sync(0xffffffffu, rs0, 1);
        rs0 += __shfl_xor_sync(0xffffffffu, rs0, 2);
        rs1 += __shfl_xor_sync(0xffffffffu, rs1, 1);
        rs1 += __shfl_xor_sync(0xffffffffu, rs1, 2);
        l_i[0] = l_i[0] * c0 + rs0;
        l_i[1] = l_i[1] * c1 + rs1;

        #pragma unroll
        for (int nt = 0; nt < 8; nt++) {
            o[nt][0] *= c0; o[nt][1] *= c0;
            o[nt][2] *= c1; o[nt][3] *= c1;
        }

        #pragma unroll
        for (int kc = 0; kc < 4; kc++) {
            unsigned pa[4];
            pa[0] = pack2_bf16(s[2 * kc][0],     s[2 * kc][1]);
            pa[1] = pack2_bf16(s[2 * kc][2],     s[2 * kc][3]);
            pa[2] = pack2_bf16(s[2 * kc + 1][0], s[2 * kc + 1][1]);
            pa[3] = pack2_bf16(s[2 * kc + 1][2], s[2 * kc + 1][3]);
            #pragma unroll
            for (int dp = 0; dp < 4; dp++) {
                unsigned rr[4];
                ldm_x4_trans(Vbase +
                    (unsigned)(((kc * 16 + bkrow) * FA_ST + dp * 16 + bncol) * 2), rr);
                unsigned vb0[2] = {rr[0], rr[1]};
                unsigned vb1[2] = {rr[2], rr[3]};
                mma_bf16(o[2 * dp],     pa, vb0);
                mma_bf16(o[2 * dp + 1], pa, vb1);
            }
        }
    }

    float inv0 = 1.0f / l_i[0];
    float inv1 = 1.0f / l_i[1];
    int row0 = token0 + seq * n + q0 + warp * 16 + g;
    #pragma unroll
    for (int nt = 0; nt < 8; nt++) {
        int col = head * HD + nt * 8 + 2 * t;
        *(bf162*)(out + (size_t)row0 * D + col) =
            __floats2bfloat162_rn(o[nt][0] * inv0, o[nt][1] * inv0);
        *(bf162*)(out + (size_t)(row0 + 8) * D + col) =
            __floats2bfloat162_rn(o[nt][2] * inv1, o[nt][3] * inv1);
    }
}

// ---------------- launch ----------------
extern "C" void kernel_launch(void* const* d_in, const int* in_sizes, int n_in,
                              void* d_out, int out_size)
{
    const float* x1     = (const float*)d_in[0];
    const float* x2     = (const float*)d_in[1];
    const float* ln1_g  = (const float*)d_in[2];
    const float* ln1_b  = (const float*)d_in[3];
    const float* w_qkv  = (const float*)d_in[4];
    const float* b_qkv  = (const float*)d_in[5];
    const float* w_proj = (const float*)d_in[6];
    const float* b_proj = (const float*)d_in[7];
    const float* ls1    = (const float*)d_in[8];
    const float* ln2_g  = (const float*)d_in[9];
    const float* ln2_b  = (const float*)d_in[10];
    const float* w_fc1  = (const float*)d_in[11];
    const float* b_fc1  = (const float*)d_in[12];
    const float* w_fc2  = (const float*)d_in[13];
    const float* b_fc2  = (const float*)d_in[14];
    const float* ls2    = (const float*)d_in[15];
    float* out = (float*)d_out;

    float *xbuf, *xmidbuf;
    bf16 *hbuf, *qkvbuf, *attbuf, *ffbuf, *wqkvh, *wprojh, *wfc1h, *wfc2h;
    cudaGetSymbolAddress((void**)&xbuf,   g_x);
    cudaGetSymbolAddress((void**)&xmidbuf,g_xmid);
    cudaGetSymbolAddress((void**)&hbuf,   g_h);
    cudaGetSymbolAddress((void**)&qkvbuf, g_qkvh);
    cudaGetSymbolAddress((void**)&attbuf, g_atth);
    cudaGetSymbolAddress((void**)&ffbuf,  g_ffh);
    cudaGetSymbolAddress((void**)&wqkvh,  g_wqkv);
    cudaGetSymbolAddress((void**)&wprojh, g_wproj);
    cudaGetSymbolAddress((void**)&wfc1h,  g_wfc1);
    cudaGetSymbolAddress((void**)&wfc2h,  g_wfc2);

    cudaFuncSetAttribute(gemm_bf16<0>, cudaFuncAttributeMaxDynamicSharedMemorySize, GEMM_SMEM);
    cudaFuncSetAttribute(gemm_bf16<1>, cudaFuncAttributeMaxDynamicSharedMemorySize, GEMM_SMEM);
    cudaFuncSetAttribute(gemm_bf16<2>, cudaFuncAttributeMaxDynamicSharedMemorySize, GEMM_SMEM);

    // 0. weights -> bf16
    cvt_kernel<<<512, 256>>>(w_qkv,  wqkvh,  D * 3 * D);
    cvt_kernel<<<256, 256>>>(w_proj, wprojh, D * D);
    cvt_kernel<<<512, 256>>>(w_fc1,  wfc1h,  D * FF_DIM);
    cvt_kernel<<<512, 256>>>(w_fc2,  wfc2h,  FF_DIM * D);

    // 1. gather + LN1 (bf16 h, fp32 residual copy)
    ln_kernel<<<NTOK, 256>>>(x1, x2, NTOK_A, ln1_g, ln1_b, hbuf, xbuf);

    // 2. QKV GEMM -> bf16
    gemm_bf16<0><<<dim3(2304 / BN, NTOK / BM), 256, GEMM_SMEM>>>(
        hbuf, wqkvh, b_qkv, nullptr, nullptr, qkvbuf, NTOK, 2304, D);

    // 3. flash attention
    fattn_kernel<<<8 * NH * (512 / FA_QT), 128>>>(qkvbuf, attbuf, 512, 0);
    fattn_kernel<<<8 * NH * (1024 / FA_QT), 128>>>(qkvbuf, attbuf, 1024, NTOK_A);

    // 4. proj GEMM + layerscale + residual -> fp32 xmid
    gemm_bf16<1><<<dim3(768 / BN, NTOK / BM), 256, GEMM_SMEM>>>(
        attbuf, wprojh, b_proj, ls1, xbuf, xmidbuf, NTOK, D, D);

    // 5. LN2 -> bf16 h
    ln_kernel<<<NTOK, 256>>>(xmidbuf, xmidbuf, NTOK, ln2_g, ln2_b, hbuf, nullptr);

    // 6. FC1 GEMM + GELU -> bf16 ff
    gemm_bf16<2><<<dim3(FF_DIM / BN, NTOK / BM), 256, GEMM_SMEM>>>(
        hbuf, wfc1h, b_fc1, nullptr, nullptr, ffbuf, NTOK, FF_DIM, D);

    // 7. FC2 GEMM + layerscale + residual -> fp32 out
    gemm_bf16<1><<<dim3(768 / BN, NTOK / BM), 256, GEMM_SMEM>>>(
        ffbuf, wfc2h, b_fc2, ls2, xmidbuf, out, NTOK, D, FF_DIM);
}

// round 10
// speedup vs baseline: 7.4340x; 1.2908x over previous
#include <cuda_runtime.h>
#include <cuda_bf16.h>
#include <stdint.h>
#include <math.h>

#define D 768
#define NH 12
#define HD 64
#define FF_DIM 3072
#define NTOK 12288
#define NTOK_A 4096   // 8 seqs * 512

typedef __nv_bfloat16 bf16;
typedef __nv_bfloat162 bf162;

// ---------------- scratch ----------------
__device__ float g_x   [NTOK * D];                 // residual (fp32)
__device__ float g_xmid[NTOK * D];                 // post-attn residual (fp32)
__device__ bf16  g_h   [NTOK * D];                 // LN out (bf16)
__device__ bf16  g_qkvh[(size_t)NTOK * 3 * D];     // QKV (bf16)
__device__ bf16  g_atth[NTOK * D];                 // attention out (bf16)
__device__ bf16  g_ffh [(size_t)NTOK * FF_DIM];    // GELU out (bf16)
// bf16 weights [K, N]
__device__ bf16  g_wqkv [D * 3 * D];
__device__ bf16  g_wproj[D * D];
__device__ bf16  g_wfc1 [D * FF_DIM];
__device__ bf16  g_wfc2 [FF_DIM * D];

// ---------------- fp32 -> bf16 convert ----------------
__global__ void cvt_kernel(const float* __restrict__ src, bf16* __restrict__ dst, int n)
{
    int i = (blockIdx.x * 256 + threadIdx.x) * 4;
    int stride = gridDim.x * 256 * 4;
    for (; i < n; i += stride) {
        float4 f = *(const float4*)(src + i);
        bf162 p0 = __floats2bfloat162_rn(f.x, f.y);
        bf162 p1 = __floats2bfloat162_rn(f.z, f.w);
        *(bf162*)(dst + i)     = p0;
        *(bf162*)(dst + i + 2) = p1;
    }
}

// ---------------- LayerNorm (fp32 in, bf16 out, optional fp32 copy) --------
__global__ void ln_kernel(const float* __restrict__ srcA,
                          const float* __restrict__ srcB,
                          int splitRow,
                          const float* __restrict__ gamma,
                          const float* __restrict__ beta,
                          bf16* __restrict__ out,
                          float* __restrict__ copy)
{
    int row = blockIdx.x;
    const float* src = (row < splitRow) ? srcA + (size_t)row * D
                                        : srcB + (size_t)(row - splitRow) * D;
    int t = threadIdx.x;
    float v0 = src[t], v1 = src[t + 256], v2 = src[t + 512];

    __shared__ float s1[256], s2[256];
    s1[t] = v0 + v1 + v2;
    s2[t] = v0 * v0 + v1 * v1 + v2 * v2;
    __syncthreads();
    for (int s = 128; s > 0; s >>= 1) {
        if (t < s) { s1[t] += s1[t + s]; s2[t] += s2[t + s]; }
        __syncthreads();
    }
    float m    = s1[0] * (1.0f / 768.0f);
    float var  = s2[0] * (1.0f / 768.0f) - m * m;
    float rstd = rsqrtf(var + 1e-5f);

    bf16* o = out + (size_t)row * D;
    o[t]       = __float2bfloat16((v0 - m) * rstd * gamma[t]       + beta[t]);
    o[t + 256] = __float2bfloat16((v1 - m) * rstd * gamma[t + 256] + beta[t + 256]);
    o[t + 512] = __float2bfloat16((v2 - m) * rstd * gamma[t + 512] + beta[t + 512]);
    if (copy) {
        float* c = copy + (size_t)row * D;
        c[t] = v0; c[t + 256] = v1; c[t + 512] = v2;
    }
}

// ---------------- common MMA helpers ----------------
__device__ __forceinline__ void cp_async16(unsigned saddr, const void* gptr) {
    asm volatile("cp.async.cg.shared.global [%0], [%1], 16;" :: "r"(saddr), "l"(gptr));
}
__device__ __forceinline__ void cp_commit() {
    asm volatile("cp.async.commit_group;");
}
template <int N>
__device__ __forceinline__ void cp_wait() {
    asm volatile("cp.async.wait_group %0;" :: "n"(N));
}
__device__ __forceinline__ void ldm_x4(unsigned saddr, unsigned* r) {
    asm volatile("ldmatrix.sync.aligned.m8n8.x4.shared.b16 {%0,%1,%2,%3}, [%4];"
                 : "=r"(r[0]), "=r"(r[1]), "=r"(r[2]), "=r"(r[3]) : "r"(saddr));
}
__device__ __forceinline__ void ldm_x4_trans(unsigned saddr, unsigned* r) {
    asm volatile("ldmatrix.sync.aligned.m8n8.x4.trans.shared.b16 {%0,%1,%2,%3}, [%4];"
                 : "=r"(r[0]), "=r"(r[1]), "=r"(r[2]), "=r"(r[3]) : "r"(saddr));
}
__device__ __forceinline__ void mma_bf16(float* c, const unsigned* a, const unsigned* b) {
    asm volatile(
        "mma.sync.aligned.m16n8k16.row.col.f32.bf16.bf16.f32 "
        "{%0,%1,%2,%3}, {%4,%5,%6,%7}, {%8,%9}, {%0,%1,%2,%3};"
        : "+f"(c[0]), "+f"(c[1]), "+f"(c[2]), "+f"(c[3])
        : "r"(a[0]), "r"(a[1]), "r"(a[2]), "r"(a[3]), "r"(b[0]), "r"(b[1]));
}
__device__ __forceinline__ unsigned pack2_bf16(float x, float y) {
    bf162 h = __floats2bfloat162_rn(x, y);
    return *reinterpret_cast<unsigned*>(&h);
}

// ---------------- bf16 mma.sync GEMM: 256x128 tile, 512 thr, 16 warps ------
// 4 warps per SMSP for latency hiding. BK=64, 3 cp.async stages.
#define BM 256
#define BN 128
#define BK 64
#define AST 72     // As row stride (bf16): 144B
#define BST 136    // Bs row stride (bf16): 272B
#define STAGES 3
#define A_STAGE (BM * AST)             // 18432 bf16
#define B_STAGE (BK * BST)             // 8704 bf16
#define GEMM_SMEM ((STAGES * (A_STAGE + B_STAGE)) * 2)   // 162816 B

// stage issue: A 256x64 (4 chunks/thr), B 64x128 (2 chunks/thr)
__device__ __forceinline__ void gemm_issue_stage(
    const bf16* AgBase, const bf16* BgBase, bf16* As, bf16* Bs,
    int kt, int s, int K, int N,
    int aRow, int aCol, int bRow, int bCol)
{
    const bf16* Ag = AgBase + kt * BK;
    bf16* Asb = As + s * A_STAGE;
    #pragma unroll
    for (int i = 0; i < 4; i++) {
        int col = aCol + 8 * i;
        cp_async16((unsigned)__cvta_generic_to_shared(Asb + aRow * AST + col),
                   Ag + (size_t)aRow * K + col);
    }
    const bf16* Bg = BgBase + (size_t)(kt * BK) * N;
    bf16* Bsb = Bs + s * B_STAGE;
    #pragma unroll
    for (int i = 0; i < 2; i++) {
        int col = bCol + 8 * i;
        cp_async16((unsigned)__cvta_generic_to_shared(Bsb + bRow * BST + col),
                   Bg + (size_t)bRow * N + col);
    }
    cp_commit();
}

template <int EPI>
__global__ __launch_bounds__(512)
void gemm_bf16(const bf16* __restrict__ A, const bf16* __restrict__ B,
               const float* __restrict__ bias, const float* __restrict__ ls,
               const float* __restrict__ res, void* __restrict__ Cout,
               int M, int N, int K)
{
    extern __shared__ __align__(16) char smem_raw[];
    bf16* As = (bf16*)smem_raw;
    bf16* Bs = As + STAGES * A_STAGE;

    const int bx = blockIdx.x, by = blockIdx.y;
    const int tid = threadIdx.x;
    const int warp = tid >> 5, lane = tid & 31;
    const int wm = (warp & 3) * 64;        // 4 m-groups
    const int wn = (warp >> 2) * 32;       // 4 n-groups
    const int group = lane >> 2, tig = lane & 3;

    // staging layout
    const int aRow = tid >> 1, aCol = (tid & 1) * 32;   // 256 rows x 2 col-halves
    const int bRow = tid >> 3, bCol = (tid & 7) * 16;   // 64 rows x 8 col-pairs

    const bf16* AgBase = A + (size_t)(by * BM) * K;
    const bf16* BgBase = B + (size_t)(bx * BN);

    const int iters = K / BK;

    float acc[4][4][4];
    #pragma unroll
    for (int mt = 0; mt < 4; mt++)
        #pragma unroll
        for (int nt = 0; nt < 4; nt++) {
            acc[mt][nt][0] = 0.f; acc[mt][nt][1] = 0.f;
            acc[mt][nt][2] = 0.f; acc[mt][nt][3] = 0.f;
        }

    const int a_row = wm + (lane & 15);
    const int a_col = (lane >> 4) * 8;
    const int b_krow = ((lane >> 3) & 1) * 8 + (lane & 7);
    const int b_ncol = wn + (lane >> 4) * 8;

    gemm_issue_stage(AgBase, BgBase, As, Bs, 0, 0, K, N, aRow, aCol, bRow, bCol);
    gemm_issue_stage(AgBase, BgBase, As, Bs, 1, 1, K, N, aRow, aCol, bRow, bCol);

    for (int it = 0; it < iters; it++) {
        cp_wait<STAGES - 2>();
        __syncthreads();

        if (it + 2 < iters)
            gemm_issue_stage(AgBase, BgBase, As, Bs,
                             it + 2, (it + 2) % STAGES, K, N,
                             aRow, aCol, bRow, bCol);

        const int s = it % STAGES;
        unsigned As_base = (unsigned)__cvta_generic_to_shared(As + s * A_STAGE);
        unsigned Bs_base = (unsigned)__cvta_generic_to_shared(Bs + s * B_STAGE);

        #pragma unroll
        for (int kstep = 0; kstep < 4; kstep++) {
            const int k0 = kstep * 16;
            unsigned afr[4][4];
            unsigned bfr[4][2];
            #pragma unroll
            for (int mt = 0; mt < 4; mt++) {
                unsigned ad = As_base +
                    (unsigned)(((a_row + mt * 16) * AST + k0 + a_col) * 2);
                ldm_x4(ad, afr[mt]);
            }
            #pragma unroll
            for (int np = 0; np < 2; np++) {
                unsigned bd = Bs_base +
                    (unsigned)(((k0 + b_krow) * BST + b_ncol + np * 16) * 2);
                unsigned rr[4];
                ldm_x4_trans(bd, rr);
                bfr[2 * np][0] = rr[0]; bfr[2 * np][1] = rr[1];
                bfr[2 * np + 1][0] = rr[2]; bfr[2 * np + 1][1] = rr[3];
            }
            #pragma unroll
            for (int mt = 0; mt < 4; mt++)
                #pragma unroll
                for (int nt = 0; nt < 4; nt++)
                    mma_bf16(acc[mt][nt], afr[mt], bfr[nt]);
        }
    }

    #pragma unroll
    for (int mt = 0; mt < 4; mt++) {
        #pragma unroll
        for (int nt = 0; nt < 4; nt++) {
            int row0 = by * BM + wm + mt * 16 + group;
            int col0 = bx * BN + wn + nt * 8 + tig * 2;
            #pragma unroll
            for (int half = 0; half < 2; half++) {
                int row = row0 + half * 8;
                float v0 = acc[mt][nt][2 * half]     + bias[col0];
                float v1 = acc[mt][nt][2 * half + 1] + bias[col0 + 1];
                size_t idx = (size_t)row * N + col0;
                if (EPI == 0) {
                    *(bf162*)((bf16*)Cout + idx) = __floats2bfloat162_rn(v0, v1);
                } else if (EPI == 1) {
                    float2 r2 = *(const float2*)(res + idx);
                    *(float2*)((float*)Cout + idx) =
                        make_float2(r2.x + ls[col0] * v0,
                                    r2.y + ls[col0 + 1] * v1);
                } else {
                    float g0 = 0.5f * v0 * (1.0f + erff(v0 * 0.70710678118654752f));
                    float g1 = 0.5f * v1 * (1.0f + erff(v1 * 0.70710678118654752f));
                    *(bf162*)((bf16*)Cout + idx) = __floats2bfloat162_rn(g0, g1);
                }
            }
        }
    }
}

// ---------------- Flash attention (bf16 mma.sync) ----------------
#define FA_QT 64
#define FA_KT 64
#define FA_ST 72

__global__ __launch_bounds__(128)
void fattn_kernel(const bf16* __restrict__ qkv,
                  bf16* __restrict__ out,
                  int n, int token0)
{
    const int qtiles = n / FA_QT;
    int b    = blockIdx.x;
    int qt   = b % qtiles;
    int r    = b / qtiles;
    int head = r % NH;
    int seq  = r / NH;
    const size_t base = (size_t)(token0 + seq * n) * (3 * D);
    const int q0 = qt * FA_QT;

    __shared__ __align__(16) bf16 Qs[FA_QT * FA_ST];
    __shared__ __align__(16) bf16 Ks[FA_KT * FA_ST];
    __shared__ __align__(16) bf16 Vs[FA_KT * FA_ST];

    const int tid  = threadIdx.x;
    const int warp = tid >> 5, lane = tid & 31;
    const int g = lane >> 2, t = lane & 3;

    const bf162 sc = __float2bfloat162_rn(0.125f);
    for (int i = tid; i < FA_QT * 8; i += 128) {
        int row = i >> 3, c = (i & 7) * 8;
        uint4 v = *(const uint4*)(qkv + base + (size_t)(q0 + row) * (3 * D) + head * HD + c);
        bf162* p = (bf162*)&v;
        #pragma unroll
        for (int j = 0; j < 4; j++) p[j] = __hmul2(p[j], sc);
        *(uint4*)(&Qs[row * FA_ST + c]) = v;
    }
    __syncthreads();

    unsigned Qbase = (unsigned)__cvta_generic_to_shared(Qs);
    unsigned Kbase = (unsigned)__cvta_generic_to_shared(Ks);
    unsigned Vbase = (unsigned)__cvta_generic_to_shared(Vs);
    const int arow  = warp * 16 + (lane & 15);
    const int acol  = (lane >> 4) * 8;
    const int bkrow = ((lane >> 3) & 1) * 8 + (lane & 7);
    const int bncol = (lane >> 4) * 8;

    unsigned qf[4][4];
    #pragma unroll
    for (int dc = 0; dc < 4; dc++)
        ldm_x4(Qbase + (unsigned)((arow * FA_ST + dc * 16 + acol) * 2), qf[dc]);

    float m_i[2] = {-1e30f, -1e30f};
    float l_i[2] = {0.f, 0.f};
    float o[8][4];
    #pragma unroll
    for (int nt = 0; nt < 8; nt++) {
        o[nt][0] = 0.f; o[nt][1] = 0.f; o[nt][2] = 0.f; o[nt][3] = 0.f;
    }

    const int ktiles = n / FA_KT;
    for (int kt = 0; kt < ktiles; kt++) {
        __syncthreads();
        for (int i = tid; i < FA_KT * 8; i += 128) {
            int row = i >> 3, c = (i & 7) * 8;
            const bf16* src = qkv + base + (size_t)(kt * FA_KT + row) * (3 * D) + head * HD + c;
            *(uint4*)(&Ks[row * FA_ST + c]) = *(const uint4*)(src + D);
            *(uint4*)(&Vs[row * FA_ST + c]) = *(const uint4*)(src + 2 * D);
        }
        __syncthreads();

        float s[8][4];
        #pragma unroll
        for (int nt = 0; nt < 8; nt++) {
            s[nt][0] = 0.f; s[nt][1] = 0.f; s[nt][2] = 0.f; s[nt][3] = 0.f;
        }
        #pragma unroll
        for (int dc = 0; dc < 4; dc++) {
            #pragma unroll
            for (int ng = 0; ng < 4; ng++) {
                unsigned kf[4];
                ldm_x4(Kbase + (unsigned)(((ng * 16 + (lane & 15)) * FA_ST + dc * 16 + acol) * 2), kf);
                unsigned b0[2] = {kf[0], kf[2]};
                unsigned b1[2] = {kf[1], kf[3]};
                mma_bf16(s[2 * ng],     qf[dc], b0);
                mma_bf16(s[2 * ng + 1], qf[dc], b1);
            }
        }

        float rmax0 = -1e30f, rmax1 = -1e30f;
        #pragma unroll
        for (int nt = 0; nt < 8; nt++) {
            rmax0 = fmaxf(rmax0, fmaxf(s[nt][0], s[nt][1]));
            rmax1 = fmaxf(rmax1, fmaxf(s[nt][2], s[nt][3]));
        }
        rmax0 = fmaxf(rmax0, __shfl_xor_sync(0xffffffffu, rmax0, 1));
        rmax0 = fmaxf(rmax0, __shfl_xor_sync(0xffffffffu, rmax0, 2));
        rmax1 = fmaxf(rmax1, __shfl_xor_sync(0xffffffffu, rmax1, 1));
        rmax1 = fmaxf(rmax1, __shfl_xor_sync(0xffffffffu, rmax1, 2));

        float mn0 = fmaxf(m_i[0], rmax0);
        float mn1 = fmaxf(m_i[1], rmax1);
        float c0 = __expf(m_i[0] - mn0);
        float c1 = __expf(m_i[1] - mn1);
        m_i[0] = mn0; m_i[1] = mn1;

        float rs0 = 0.f, rs1 = 0.f;
        #pragma unroll
        for (int nt = 0; nt < 8; nt++) {
            s[nt][0] = __expf(s[nt][0] - mn0);
            s[nt][1] = __expf(s[nt][1] - mn0);
            s[nt][2] = __expf(s[nt][2] - mn1);
            s[nt][3] = __expf(s[nt][3] - mn1);
            rs0 += s[nt][0] + s[nt][1];
            rs1 += s[nt][2] + s[nt][3];
        }
        rs0 += __shfl_xor_sync(0xffffffffu, rs0, 1);
        rs0 += __shfl_xor_sync(0xffffffffu, rs0, 2);
        rs1 += __shfl_xor_sync(0xffffffffu, rs1, 1);
        rs1 += __shfl_xor_sync(0xffffffffu, rs1, 2);
        l_i[0] = l_i[0] * c0 + rs0;
        l_i[1] = l_i[1] * c1 + rs1;

        #pragma unroll
        for (int nt = 0; nt < 8; nt++) {
            o[nt][0] *= c0; o[nt][1] *= c0;
            o[nt][2] *= c1; o[nt][3] *= c1;
        }

        #pragma unroll
        for (int kc = 0; kc < 4; kc++) {
            unsigned pa[4];
            pa[0] = pack2_bf16(s[2 * kc][0],     s[2 * kc][1]);
            pa[1] = pack2_bf16(s[2 * kc][2],     s[2 * kc][3]);
            pa[2] = pack2_bf16(s[2 * kc + 1][0], s[2 * kc + 1][1]);
            pa[3] = pack2_bf16(s[2 * kc + 1][2], s[2 * kc + 1][3]);
            #pragma unroll
            for (int dp = 0; dp < 4; dp++) {
                unsigned rr[4];
                ldm_x4_trans(Vbase +
                    (unsigned)(((kc * 16 + bkrow) * FA_ST + dp * 16 + bncol) * 2), rr);
                unsigned vb0[2] = {rr[0], rr[1]};
                unsigned vb1[2] = {rr[2], rr[3]};
                mma_bf16(o[2 * dp],     pa, vb0);
                mma_bf16(o[2 * dp + 1], pa, vb1);
            }
        }
    }

    float inv0 = 1.0f / l_i[0];
    float inv1 = 1.0f / l_i[1];
    int row0 = token0 + seq * n + q0 + warp * 16 + g;
    #pragma unroll
    for (int nt = 0; nt < 8; nt++) {
        int col = head * HD + nt * 8 + 2 * t;
        *(bf162*)(out + (size_t)row0 * D + col) =
            __floats2bfloat162_rn(o[nt][0] * inv0, o[nt][1] * inv0);
        *(bf162*)(out + (size_t)(row0 + 8) * D + col) =
            __floats2bfloat162_rn(o[nt][2] * inv1, o[nt][3] * inv1);
    }
}

// ---------------- launch ----------------
extern "C" void kernel_launch(void* const* d_in, const int* in_sizes, int n_in,
                              void* d_out, int out_size)
{
    const float* x1     = (const float*)d_in[0];
    const float* x2     = (const float*)d_in[1];
    const float* ln1_g  = (const float*)d_in[2];
    const float* ln1_b  = (const float*)d_in[3];
    const float* w_qkv  = (const float*)d_in[4];
    const float* b_qkv  = (const float*)d_in[5];
    const float* w_proj = (const float*)d_in[6];
    const float* b_proj = (const float*)d_in[7];
    const float* ls1    = (const float*)d_in[8];
    const float* ln2_g  = (const float*)d_in[9];
    const float* ln2_b  = (const float*)d_in[10];
    const float* w_fc1  = (const float*)d_in[11];
    const float* b_fc1  = (const float*)d_in[12];
    const float* w_fc2  = (const float*)d_in[13];
    const float* b_fc2  = (const float*)d_in[14];
    const float* ls2    = (const float*)d_in[15];
    float* out = (float*)d_out;

    float *xbuf, *xmidbuf;
    bf16 *hbuf, *qkvbuf, *attbuf, *ffbuf, *wqkvh, *wprojh, *wfc1h, *wfc2h;
    cudaGetSymbolAddress((void**)&xbuf,   g_x);
    cudaGetSymbolAddress((void**)&xmidbuf,g_xmid);
    cudaGetSymbolAddress((void**)&hbuf,   g_h);
    cudaGetSymbolAddress((void**)&qkvbuf, g_qkvh);
    cudaGetSymbolAddress((void**)&attbuf, g_atth);
    cudaGetSymbolAddress((void**)&ffbuf,  g_ffh);
    cudaGetSymbolAddress((void**)&wqkvh,  g_wqkv);
    cudaGetSymbolAddress((void**)&wprojh, g_wproj);
    cudaGetSymbolAddress((void**)&wfc1h,  g_wfc1);
    cudaGetSymbolAddress((void**)&wfc2h,  g_wfc2);

    cudaFuncSetAttribute(gemm_bf16<0>, cudaFuncAttributeMaxDynamicSharedMemorySize, GEMM_SMEM);
    cudaFuncSetAttribute(gemm_bf16<1>, cudaFuncAttributeMaxDynamicSharedMemorySize, GEMM_SMEM);
    cudaFuncSetAttribute(gemm_bf16<2>, cudaFuncAttributeMaxDynamicSharedMemorySize, GEMM_SMEM);

    // 0. weights -> bf16
    cvt_kernel<<<512, 256>>>(w_qkv,  wqkvh,  D * 3 * D);
    cvt_kernel<<<256, 256>>>(w_proj, wprojh, D * D);
    cvt_kernel<<<512, 256>>>(w_fc1,  wfc1h,  D * FF_DIM);
    cvt_kernel<<<512, 256>>>(w_fc2,  wfc2h,  FF_DIM * D);

    // 1. gather + LN1 (bf16 h, fp32 residual copy)
    ln_kernel<<<NTOK, 256>>>(x1, x2, NTOK_A, ln1_g, ln1_b, hbuf, xbuf);

    // 2. QKV GEMM -> bf16
    gemm_bf16<0><<<dim3(2304 / BN, NTOK / BM), 512, GEMM_SMEM>>>(
        hbuf, wqkvh, b_qkv, nullptr, nullptr, qkvbuf, NTOK, 2304, D);

    // 3. flash attention
    fattn_kernel<<<8 * NH * (512 / FA_QT), 128>>>(qkvbuf, attbuf, 512, 0);
    fattn_kernel<<<8 * NH * (1024 / FA_QT), 128>>>(qkvbuf, attbuf, 1024, NTOK_A);

    // 4. proj GEMM + layerscale + residual -> fp32 xmid
    gemm_bf16<1><<<dim3(768 / BN, NTOK / BM), 512, GEMM_SMEM>>>(
        attbuf, wprojh, b_proj, ls1, xbuf, xmidbuf, NTOK, D, D);

    // 5. LN2 -> bf16 h
    ln_kernel<<<NTOK, 256>>>(xmidbuf, xmidbuf, NTOK, ln2_g, ln2_b, hbuf, nullptr);

    // 6. FC1 GEMM + GELU -> bf16 ff
    gemm_bf16<2><<<dim3(FF_DIM / BN, NTOK / BM), 512, GEMM_SMEM>>>(
        hbuf, wfc1h, b_fc1, nullptr, nullptr, ffbuf, NTOK, FF_DIM, D);

    // 7. FC2 GEMM + layerscale + residual -> fp32 out
    gemm_bf16<1><<<dim3(768 / BN, NTOK / BM), 512, GEMM_SMEM>>>(
        ffbuf, wfc2h, b_fc2, ls2, xmidbuf, out, NTOK, FF_DIM == 0 ? 0 : 768, FF_DIM);
}